// round 2
// baseline (speedup 1.0000x reference)
#include <cuda_runtime.h>
#include <cstdint>

// Problem constants (fixed by setup_inputs)
#define B_  8
#define N_  6144
#define D_  16
#define K_  3
#define O_  64
#define BD_ 128   // B*D columns of the aggregation GEMM

// Scratch (no cudaMalloc allowed)
__device__ float g_Xt[N_ * BD_];                       // X transposed: [m][b*16+d], 3.1 MB
__device__ float g_Y[(size_t)K_ * N_ * BD_];           // Y_k[n][b*16+d], 9.4 MB

// ---------------- PTX helpers ----------------
__device__ __forceinline__ unsigned smem_u32(const void* p) {
    return (unsigned)__cvta_generic_to_shared(p);
}
__device__ __forceinline__ void cp_async16(const void* smem_dst, const void* gsrc) {
    asm volatile("cp.async.cg.shared.global [%0], [%1], 16;\n"
                 :: "r"(smem_u32(smem_dst)), "l"(gsrc));
}
__device__ __forceinline__ void cp_commit() {
    asm volatile("cp.async.commit_group;\n" ::: "memory");
}
template<int NWAIT>
__device__ __forceinline__ void cp_wait() {
    asm volatile("cp.async.wait_group %0;\n" :: "n"(NWAIT) : "memory");
}
__device__ __forceinline__ unsigned long long pack2(float x, float y) {
    unsigned long long r;
    asm("mov.b64 %0, {%1, %2};" : "=l"(r) : "f"(x), "f"(y));
    return r;
}
__device__ __forceinline__ void unpack2(unsigned long long v, float& x, float& y) {
    asm("mov.b64 {%0, %1}, %2;" : "=f"(x), "=f"(y) : "l"(v));
}
// Packed dual-fp32 FMA (Blackwell f32x2 pipe; 2x FFMA throughput)
__device__ __forceinline__ void fma2(unsigned long long& c,
                                     unsigned long long a,
                                     unsigned long long b) {
    asm("fma.rn.f32x2 %0, %1, %2, %0;" : "+l"(c) : "l"(a), "l"(b));
}
// 16B shared load straight into two packed b64 operands (no unpack movs)
__device__ __forceinline__ void lds_2xu64(unsigned long long& a,
                                          unsigned long long& b,
                                          const void* p) {
    asm("ld.shared.v2.u64 {%0, %1}, [%2];" : "=l"(a), "=l"(b) : "r"(smem_u32(p)));
}

// ---------------- Kernel 0: build X^T  [m][b*16+d] ----------------
__global__ void xt_kernel(const float* __restrict__ inputs) {
    int idx = blockIdx.x * blockDim.x + threadIdx.x;
    if (idx >= N_ * BD_) return;
    int m = idx >> 7;
    int j = idx & 127;
    int b = j >> 4;
    int d = j & 15;
    g_Xt[idx] = inputs[((size_t)b * N_ + m) * D_ + d];
}

// ---------------- Kernel 1: Y_k = sup_k @ X  (fp32, f32x2-packed) ----------
// Tile: 128x128 C per block, BK=16, 256 threads, 8x8 micro-tile per thread.
// cp.async double-buffered. grid = (48 row-tiles, 3 supports) = 144 blocks.
__global__ __launch_bounds__(256, 1)
void gemm_kernel(const float* __restrict__ supports) {
    __shared__ float As[2][128][16];   // [buf][row][k]
    __shared__ float Xs[2][16][128];   // [buf][k][col]

    const int t    = threadIdx.x;
    const int tx   = t & 15;           // column group
    const int ty   = t >> 4;           // row group
    const int row0 = blockIdx.x * 128;
    const int ksup = blockIdx.y;

    const float* A = supports + (size_t)ksup * N_ * N_;
    float*       C = g_Y      + (size_t)ksup * N_ * BD_;

    // loader lane mapping
    const int a_row = t >> 2;          // 0..63 (+64 for second half)
    const int a_c4  = (t & 3) << 2;    // 0,4,8,12
    const int x_kr  = t >> 5;          // 0..7 (+8 for second half)
    const int x_c   = (t & 31) << 2;   // 0..124

    const int cx    = tx << 2;         // cols cx..cx+3 and cx+64..cx+67
    const int rbase = ty << 2;         // rows rbase..+3 and 64+rbase..+3

    unsigned long long acc[8][4];
    #pragma unroll
    for (int i = 0; i < 8; ++i)
        #pragma unroll
        for (int p = 0; p < 4; ++p) acc[i][p] = 0ull;

    // prologue: stage 0
    cp_async16(&As[0][a_row][a_c4],      &A[(size_t)(row0 + a_row) * N_ + a_c4]);
    cp_async16(&As[0][a_row + 64][a_c4], &A[(size_t)(row0 + a_row + 64) * N_ + a_c4]);
    cp_async16(&Xs[0][x_kr][x_c],        &g_Xt[(x_kr) * BD_ + x_c]);
    cp_async16(&Xs[0][x_kr + 8][x_c],    &g_Xt[(x_kr + 8) * BD_ + x_c]);
    cp_commit();

    const int NSTEP = N_ / 16;   // 384
    for (int kt = 0; kt < NSTEP; ++kt) {
        const int buf = kt & 1;
        if (kt + 1 < NSTEP) {
            const int kk = (kt + 1) * 16;
            const int nb = buf ^ 1;
            cp_async16(&As[nb][a_row][a_c4],      &A[(size_t)(row0 + a_row) * N_ + kk + a_c4]);
            cp_async16(&As[nb][a_row + 64][a_c4], &A[(size_t)(row0 + a_row + 64) * N_ + kk + a_c4]);
            cp_async16(&Xs[nb][x_kr][x_c],        &g_Xt[(size_t)(kk + x_kr) * BD_ + x_c]);
            cp_async16(&Xs[nb][x_kr + 8][x_c],    &g_Xt[(size_t)(kk + x_kr + 8) * BD_ + x_c]);
            cp_commit();
            cp_wait<1>();    // stage kt complete (FIFO)
        } else {
            cp_wait<0>();
        }
        __syncthreads();

        #pragma unroll
        for (int kc = 0; kc < 4; ++kc) {
            // hoist A operands: one float4 per row per 4-k chunk
            float4 a4[8];
            #pragma unroll
            for (int i = 0; i < 8; ++i) {
                const int r = (i < 4) ? (rbase + i) : (64 + rbase + i - 4);
                a4[i] = *reinterpret_cast<const float4*>(&As[buf][r][kc << 2]);
            }
            #pragma unroll
            for (int kq = 0; kq < 4; ++kq) {
                const int kki = (kc << 2) + kq;
                unsigned long long bb0, bb1, bb2, bb3;
                lds_2xu64(bb0, bb1, &Xs[buf][kki][cx]);
                lds_2xu64(bb2, bb3, &Xs[buf][kki][cx + 64]);
                #pragma unroll
                for (int i = 0; i < 8; ++i) {
                    const float av = (kq == 0) ? a4[i].x :
                                     (kq == 1) ? a4[i].y :
                                     (kq == 2) ? a4[i].z : a4[i].w;
                    const unsigned long long aa = pack2(av, av);
                    fma2(acc[i][0], aa, bb0);
                    fma2(acc[i][1], aa, bb1);
                    fma2(acc[i][2], aa, bb2);
                    fma2(acc[i][3], aa, bb3);
                }
            }
        }
        __syncthreads();   // protect buf before the kt+2 loader overwrites it
    }

    // epilogue: coalesced float4 stores
    #pragma unroll
    for (int i = 0; i < 8; ++i) {
        const int r = (i < 4) ? (rbase + i) : (64 + rbase + i - 4);
        float* dst = C + (size_t)(row0 + r) * BD_;
        float4 v;
        unpack2(acc[i][0], v.x, v.y);
        unpack2(acc[i][1], v.z, v.w);
        *reinterpret_cast<float4*>(dst + cx) = v;
        unpack2(acc[i][2], v.x, v.y);
        unpack2(acc[i][3], v.z, v.w);
        *reinterpret_cast<float4*>(dst + cx + 64) = v;
    }
}

// ---------------- Kernel 2: out = (Y + I-term) @ W^T + b -------------------
// Block: 32 n-rows for one batch b. Identity contribution added here
// (sup = supports + I  =>  y[b,n,d,k] += inputs[b,n,d]).
__global__ __launch_bounds__(256)
void out_kernel(const float* __restrict__ inputs,
                const float* __restrict__ W,
                const float* __restrict__ bias,
                float* __restrict__ out) {
    __shared__ float Ysh[32][49];
    __shared__ float Wsh[64][49];
    __shared__ float Bsh[64];

    const int b  = blockIdx.y;
    const int n0 = blockIdx.x * 32;
    const int t  = threadIdx.x;

    for (int idx = t; idx < 64 * 48; idx += 256)
        Wsh[idx / 48][idx % 48] = W[idx];
    if (t < 64) Bsh[t] = bias[t];

    for (int idx = t; idx < 32 * 48; idx += 256) {
        const int nn = idx / 48;
        const int j  = idx % 48;        // feature index d*3 + k
        const int d  = j / 3;
        const int kk = j % 3;
        const int n  = n0 + nn;
        Ysh[nn][j] = g_Y[(size_t)kk * N_ * BD_ + (size_t)n * BD_ + b * 16 + d]
                   + inputs[((size_t)b * N_ + n) * D_ + d];
    }
    __syncthreads();

    const int o  = t & 63;
    const int ng = t >> 6;
    #pragma unroll
    for (int r = 0; r < 8; ++r) {
        const int nn = ng * 8 + r;
        float acc = Bsh[o];
        #pragma unroll
        for (int j = 0; j < 48; ++j)
            acc += Ysh[nn][j] * Wsh[o][j];
        out[((size_t)b * N_ + n0 + nn) * O_ + o] = acc;
    }
}

// ---------------- launch ----------------
extern "C" void kernel_launch(void* const* d_in, const int* in_sizes, int n_in,
                              void* d_out, int out_size) {
    // robust size-based binding (inputs/supports/W/b have distinct sizes)
    const float* inputs = nullptr;
    const float* supports = nullptr;
    const float* W = nullptr;
    const float* bias = nullptr;
    for (int i = 0; i < n_in; ++i) {
        if      (in_sizes[i] == B_ * N_ * D_)          inputs   = (const float*)d_in[i];
        else if (in_sizes[i] == K_ * N_ * N_)          supports = (const float*)d_in[i];
        else if (in_sizes[i] == O_ * D_ * K_)          W        = (const float*)d_in[i];
        else if (in_sizes[i] == O_)                    bias     = (const float*)d_in[i];
    }
    float* out = (float*)d_out;

    xt_kernel<<<(N_ * BD_ + 255) / 256, 256>>>(inputs);
    gemm_kernel<<<dim3(N_ / 128, K_), 256>>>(supports);
    out_kernel<<<dim3(N_ / 32, B_), 256>>>(inputs, W, bias, out);
}

// round 5
// speedup vs baseline: 2.2606x; 2.2606x over previous
#include <cuda_runtime.h>
#include <cuda_bf16.h>
#include <cstdint>

// Problem constants
#define B_  8
#define N_  6144
#define D_  16
#define K_  3
#define O_  64
#define BD_ 128            // B*D columns
#define TK_ 64             // k-tile (64 bf16 = 128B row)
#define NSTEP_ (N_ / TK_)  // 96

// ------------- global scratch (no cudaMalloc allowed) ----------------------
__device__ __nv_bfloat16 g_Xh[(size_t)BD_ * N_];   // X^T hi  [col j][k]
__device__ __nv_bfloat16 g_Xl[(size_t)BD_ * N_];   // X^T lo
__device__ float         g_Y [(size_t)K_ * N_ * BD_];

// ------------- PTX helpers --------------------------------------------------
__device__ __forceinline__ unsigned smem_u32(const void* p) {
    return (unsigned)__cvta_generic_to_shared(p);
}
__device__ __forceinline__ void cp_async16(unsigned dst, const void* gsrc) {
    asm volatile("cp.async.cg.shared.global [%0], [%1], 16;\n" :: "r"(dst), "l"(gsrc));
}
__device__ __forceinline__ void cp_commit() {
    asm volatile("cp.async.commit_group;\n" ::: "memory");
}
template<int NW> __device__ __forceinline__ void cp_wait() {
    asm volatile("cp.async.wait_group %0;\n" :: "n"(NW) : "memory");
}
__device__ __forceinline__ void sts64(unsigned addr, unsigned long long v) {
    asm volatile("st.shared.b64 [%0], %1;" :: "r"(addr), "l"(v) : "memory");
}
__device__ __forceinline__ void ldsm_x4(unsigned& r0, unsigned& r1,
                                        unsigned& r2, unsigned& r3, unsigned addr) {
    asm volatile("ldmatrix.sync.aligned.m8n8.x4.shared.b16 {%0,%1,%2,%3}, [%4];"
                 : "=r"(r0), "=r"(r1), "=r"(r2), "=r"(r3) : "r"(addr));
}
// D(f32) += A(bf16) * B(bf16), m16n8k16, row.col
__device__ __forceinline__ void mma16816(float* d, const unsigned* a,
                                         const unsigned* b) {
    asm volatile(
        "mma.sync.aligned.m16n8k16.row.col.f32.bf16.bf16.f32 "
        "{%0,%1,%2,%3}, {%4,%5,%6,%7}, {%8,%9}, {%0,%1,%2,%3};"
        : "+f"(d[0]), "+f"(d[1]), "+f"(d[2]), "+f"(d[3])
        : "r"(a[0]), "r"(a[1]), "r"(a[2]), "r"(a[3]), "r"(b[0]), "r"(b[1]));
}

#define SMEM_SWIZZLE_128B(o) ((o) ^ (((o) >> 3) & 0x70))

// bf16 hi/lo split of two floats -> packed bf16x2 words
__device__ __forceinline__ void split2(float x, float y,
                                       unsigned& hpack, unsigned& lpack) {
    unsigned h;
    asm("cvt.rn.satfinite.bf16x2.f32 %0, %1, %2;" : "=r"(h) : "f"(y), "f"(x));
    float hx = __uint_as_float(h << 16);
    float hy = __uint_as_float(h & 0xFFFF0000u);
    unsigned l;
    float rx = x - hx, ry = y - hy;
    asm("cvt.rn.satfinite.bf16x2.f32 %0, %1, %2;" : "=r"(l) : "f"(ry), "f"(rx));
    hpack = h; lpack = l;
}

// ------------- smem layout (dynamic): 2 buf x 4 tiles x 16KB ----------------
#define TILE_B   (128 * TK_ * 2)                 /* 16384 bytes */
#define OFF_AH(b) ((b) * (4 * TILE_B) + 0 * TILE_B)
#define OFF_AL(b) ((b) * (4 * TILE_B) + 1 * TILE_B)
#define OFF_BH(b) ((b) * (4 * TILE_B) + 2 * TILE_B)
#define OFF_BL(b) ((b) * (4 * TILE_B) + 3 * TILE_B)
#define SMEM_BYTES (8 * TILE_B)                  /* 131072 */

// ------------- Kernel 0: split X^T into bf16 hi/lo --------------------------
__global__ void xsplit_kernel(const float* __restrict__ inputs) {
    int idx = blockIdx.x * blockDim.x + threadIdx.x;   // j*N_ + m
    if (idx >= BD_ * N_) return;
    int j = idx / N_;          // col = b*16 + d
    int m = idx % N_;
    int b = j >> 4, d = j & 15;
    float x = inputs[((size_t)b * N_ + m) * D_ + d];
    __nv_bfloat16 h = __float2bfloat16_rn(x);
    float r = x - __bfloat162float(h);
    g_Xh[idx] = h;
    g_Xl[idx] = __float2bfloat16_rn(r);
}

// ------------- Kernel 1: bf16-split GEMM via mma.sync -----------------------
// Block: C[128,128] tile of Y_k = sup_k @ X. grid = (48, 3). 256 threads.
// Warp w: rows (w/4)*64, cols (w%4)*32. Per warp: 4 m-tiles x 4 n-tiles.
__global__ __launch_bounds__(256, 1)
void gemm_mma_kernel(const float* __restrict__ supports) {
    extern __shared__ char smem_raw[];
    const unsigned sbase = smem_u32(smem_raw);

    const int t    = threadIdx.x;
    const int wid  = t >> 5;
    const int lane = t & 31;
    const int row0 = blockIdx.x * 128;

    const float* A = supports + (size_t)blockIdx.y * N_ * N_;
    float*       C = g_Y      + (size_t)blockIdx.y * N_ * BD_;

    // warp tile origin within the 128x128 block tile
    const int wm0 = (wid >> 2) * 64;    // 0 or 64
    const int wn0 = (wid & 3) * 32;     // 0,32,64,96

    // loader mapping (A): 16 threads per row, float4 each, 8 row-passes
    const int a_sub = t >> 4;           // 0..15
    const int a_c4  = (t & 15) << 2;    // float col 0,4,...,60

    // ldmatrix lane address components (element coords within tile)
    const int a_r  = lane & 15;               // row within 16-row A frag
    const int a_k8 = (lane >> 4) << 3;        // 0 or 8 (k offset)
    const int b_n  = ((lane >> 4) << 3) + (lane & 7);  // 0..15 within 16-n group
    const int b_k8 = ((lane >> 3) & 1) << 3;  // 0 or 8

    float acc[4][4][4];
    #pragma unroll
    for (int i = 0; i < 4; ++i)
        #pragma unroll
        for (int j = 0; j < 4; ++j)
            #pragma unroll
            for (int p = 0; p < 4; ++p) acc[i][j][p] = 0.f;

    float4 av[8];

    // ---- prologue: A(kt=0) regs + B(kt=0) cp.async, convert+STS A into buf0
    #pragma unroll
    for (int p = 0; p < 8; ++p)
        av[p] = __ldg(reinterpret_cast<const float4*>(
            &A[(size_t)(row0 + p * 16 + a_sub) * N_ + a_c4]));
    #pragma unroll
    for (int i = 0; i < 4; ++i) {
        const int c   = t + i * 256;          // 16B chunk (0..1023)
        const int r   = c >> 3;               // B row (n col) 0..127
        const int kin = (c & 7) << 3;         // bf16 k within tile
        const unsigned swz = SMEM_SWIZZLE_128B((unsigned)(c << 4));
        cp_async16(sbase + OFF_BH(0) + swz, &g_Xh[(size_t)r * N_ + kin]);
        cp_async16(sbase + OFF_BL(0) + swz, &g_Xl[(size_t)r * N_ + kin]);
    }
    cp_commit();
    #pragma unroll
    for (int p = 0; p < 8; ++p) {
        const int row = p * 16 + a_sub;
        const unsigned boff = (unsigned)(row * 128 + (a_c4 << 1));
        const unsigned swz  = SMEM_SWIZZLE_128B(boff);
        unsigned h01, l01, h23, l23;
        split2(av[p].x, av[p].y, h01, l01);
        split2(av[p].z, av[p].w, h23, l23);
        sts64(sbase + OFF_AH(0) + swz, ((unsigned long long)h23 << 32) | h01);
        sts64(sbase + OFF_AL(0) + swz, ((unsigned long long)l23 << 32) | l01);
    }

    for (int kt = 0; kt < NSTEP_; ++kt) {
        const int buf  = kt & 1;
        const int nbuf = buf ^ 1;

        cp_wait<0>();
        __syncthreads();   // buf tiles (cp.async B + STS A) visible; prior compute done

        // issue loads for kt+1 into nbuf (overlap with compute below)
        if (kt + 1 < NSTEP_) {
            const int kk2 = (kt + 1) * TK_;
            #pragma unroll
            for (int p = 0; p < 8; ++p)
                av[p] = __ldg(reinterpret_cast<const float4*>(
                    &A[(size_t)(row0 + p * 16 + a_sub) * N_ + kk2 + a_c4]));
            #pragma unroll
            for (int i = 0; i < 4; ++i) {
                const int c   = t + i * 256;
                const int r   = c >> 3;
                const int kin = (c & 7) << 3;
                const unsigned swz = SMEM_SWIZZLE_128B((unsigned)(c << 4));
                cp_async16(sbase + OFF_BH(nbuf) + swz, &g_Xh[(size_t)r * N_ + kk2 + kin]);
                cp_async16(sbase + OFF_BL(nbuf) + swz, &g_Xl[(size_t)r * N_ + kk2 + kin]);
            }
            cp_commit();
        }

        // ---- compute on buf: 4 k16 steps, 3 split products each
        const unsigned ah_base = sbase + OFF_AH(buf);
        const unsigned al_base = sbase + OFF_AL(buf);
        const unsigned bh_base = sbase + OFF_BH(buf);
        const unsigned bl_base = sbase + OFF_BL(buf);

        #pragma unroll
        for (int ks = 0; ks < 4; ++ks) {
            const int kk16 = ks * 16;

            unsigned ah[4][4], al[4][4];
            #pragma unroll
            for (int mt = 0; mt < 4; ++mt) {
                const unsigned off = SMEM_SWIZZLE_128B(
                    (unsigned)((wm0 + mt * 16 + a_r) * 128 + (kk16 + a_k8) * 2));
                ldsm_x4(ah[mt][0], ah[mt][1], ah[mt][2], ah[mt][3], ah_base + off);
                ldsm_x4(al[mt][0], al[mt][1], al[mt][2], al[mt][3], al_base + off);
            }
            unsigned bh[4][2], bl[4][2];
            #pragma unroll
            for (int np = 0; np < 2; ++np) {   // each x4 covers two n-tiles
                const unsigned off = SMEM_SWIZZLE_128B(
                    (unsigned)((wn0 + np * 16 + b_n) * 128 + (kk16 + b_k8) * 2));
                ldsm_x4(bh[np*2][0], bh[np*2][1], bh[np*2+1][0], bh[np*2+1][1],
                        bh_base + off);
                ldsm_x4(bl[np*2][0], bl[np*2][1], bl[np*2+1][0], bl[np*2+1][1],
                        bl_base + off);
            }
            #pragma unroll
            for (int mt = 0; mt < 4; ++mt)
                #pragma unroll
                for (int nt = 0; nt < 4; ++nt) {
                    mma16816(acc[mt][nt], ah[mt], bh[nt]);
                    mma16816(acc[mt][nt], ah[mt], bl[nt]);
                    mma16816(acc[mt][nt], al[mt], bh[nt]);
                }
        }

        // convert prefetched A regs -> bf16 hi/lo into nbuf
        if (kt + 1 < NSTEP_) {
            #pragma unroll
            for (int p = 0; p < 8; ++p) {
                const int row = p * 16 + a_sub;
                const unsigned boff = (unsigned)(row * 128 + (a_c4 << 1));
                const unsigned swz  = SMEM_SWIZZLE_128B(boff);
                unsigned h01, l01, h23, l23;
                split2(av[p].x, av[p].y, h01, l01);
                split2(av[p].z, av[p].w, h23, l23);
                sts64(sbase + OFF_AH(nbuf) + swz, ((unsigned long long)h23 << 32) | h01);
                sts64(sbase + OFF_AL(nbuf) + swz, ((unsigned long long)l23 << 32) | l01);
            }
        }
    }

    // ---- epilogue: write accumulators to g_Y (fp32)
    const int lr = lane >> 2;          // 0..7
    const int lc = (lane & 3) << 1;    // 0,2,4,6
    #pragma unroll
    for (int mt = 0; mt < 4; ++mt) {
        #pragma unroll
        for (int nt = 0; nt < 4; ++nt) {
            const int m = row0 + wm0 + mt * 16 + lr;
            const int n = wn0 + nt * 8 + lc;
            float2 v0 = make_float2(acc[mt][nt][0], acc[mt][nt][1]);
            float2 v1 = make_float2(acc[mt][nt][2], acc[mt][nt][3]);
            *reinterpret_cast<float2*>(&C[(size_t)m * BD_ + n])       = v0;
            *reinterpret_cast<float2*>(&C[(size_t)(m + 8) * BD_ + n]) = v1;
        }
    }
}

// ------------- Kernel 2: out = (Y + I-term) @ W^T + b ----------------------
__global__ __launch_bounds__(256)
void out_kernel(const float* __restrict__ inputs,
                const float* __restrict__ W,
                const float* __restrict__ bias,
                float* __restrict__ out) {
    __shared__ float Ysh[32][49];
    __shared__ float Wsh[64][49];
    __shared__ float Bsh[64];

    const int b  = blockIdx.y;
    const int n0 = blockIdx.x * 32;
    const int t  = threadIdx.x;

    for (int idx = t; idx < 64 * 48; idx += 256)
        Wsh[idx / 48][idx % 48] = W[idx];
    if (t < 64) Bsh[t] = bias[t];

    for (int idx = t; idx < 32 * 48; idx += 256) {
        const int nn = idx / 48;
        const int j  = idx % 48;        // feature index d*3 + k
        const int d  = j / 3;
        const int kk = j % 3;
        const int n  = n0 + nn;
        Ysh[nn][j] = g_Y[(size_t)kk * N_ * BD_ + (size_t)n * BD_ + b * 16 + d]
                   + inputs[((size_t)b * N_ + n) * D_ + d];
    }
    __syncthreads();

    const int o  = t & 63;
    const int ng = t >> 6;
    #pragma unroll
    for (int r = 0; r < 8; ++r) {
        const int nn = ng * 8 + r;
        float acc = Bsh[o];
        #pragma unroll
        for (int j = 0; j < 48; ++j)
            acc += Ysh[nn][j] * Wsh[o][j];
        out[((size_t)b * N_ + n0 + nn) * O_ + o] = acc;
    }
}

// ------------- launch -------------------------------------------------------
extern "C" void kernel_launch(void* const* d_in, const int* in_sizes, int n_in,
                              void* d_out, int out_size) {
    const float* inputs = nullptr;
    const float* supports = nullptr;
    const float* W = nullptr;
    const float* bias = nullptr;
    for (int i = 0; i < n_in; ++i) {
        if      (in_sizes[i] == B_ * N_ * D_) inputs   = (const float*)d_in[i];
        else if (in_sizes[i] == K_ * N_ * N_) supports = (const float*)d_in[i];
        else if (in_sizes[i] == O_ * D_ * K_) W        = (const float*)d_in[i];
        else if (in_sizes[i] == O_)           bias     = (const float*)d_in[i];
    }
    float* out = (float*)d_out;

    cudaFuncSetAttribute(gemm_mma_kernel,
                         cudaFuncAttributeMaxDynamicSharedMemorySize, SMEM_BYTES);

    xsplit_kernel<<<(BD_ * N_ + 255) / 256, 256>>>(inputs);
    gemm_mma_kernel<<<dim3(N_ / 128, K_), 256, SMEM_BYTES>>>(supports);
    out_kernel<<<dim3(N_ / 32, B_), 256>>>(inputs, W, bias, out);
}

// round 6
// speedup vs baseline: 2.3298x; 1.0306x over previous
#include <cuda_runtime.h>
#include <cuda_bf16.h>
#include <cstdint>

// Problem constants
#define B_  8
#define N_  6144
#define D_  16
#define K_  3
#define O_  64
#define BD_ 128            // B*D columns
#define TK_ 64             // k-tile (64 bf16 = 128B row)
#define NSTEP_ (N_ / TK_)  // 96

// ------------- global scratch (no cudaMalloc allowed) ----------------------
__device__ __nv_bfloat16 g_Xh[(size_t)BD_ * N_];   // X^T hi  [col j][k]
__device__ __nv_bfloat16 g_Xl[(size_t)BD_ * N_];   // X^T lo
__device__ float         g_Y [(size_t)K_ * N_ * BD_];

// ------------- PTX helpers --------------------------------------------------
__device__ __forceinline__ unsigned smem_u32(const void* p) {
    return (unsigned)__cvta_generic_to_shared(p);
}
__device__ __forceinline__ void cp_async16(unsigned dst, const void* gsrc) {
    asm volatile("cp.async.cg.shared.global [%0], [%1], 16;\n" :: "r"(dst), "l"(gsrc));
}
__device__ __forceinline__ void cp_commit() {
    asm volatile("cp.async.commit_group;\n" ::: "memory");
}
template<int NW> __device__ __forceinline__ void cp_wait() {
    asm volatile("cp.async.wait_group %0;\n" :: "n"(NW) : "memory");
}
__device__ __forceinline__ void sts64(unsigned addr, unsigned long long v) {
    asm volatile("st.shared.b64 [%0], %1;" :: "r"(addr), "l"(v) : "memory");
}
__device__ __forceinline__ void ldsm_x4(unsigned& r0, unsigned& r1,
                                        unsigned& r2, unsigned& r3, unsigned addr) {
    asm volatile("ldmatrix.sync.aligned.m8n8.x4.shared.b16 {%0,%1,%2,%3}, [%4];"
                 : "=r"(r0), "=r"(r1), "=r"(r2), "=r"(r3) : "r"(addr));
}
// D(f32) += A(bf16) * B(bf16), m16n8k16, row.col
__device__ __forceinline__ void mma16816(float* d, const unsigned* a,
                                         const unsigned* b) {
    asm volatile(
        "mma.sync.aligned.m16n8k16.row.col.f32.bf16.bf16.f32 "
        "{%0,%1,%2,%3}, {%4,%5,%6,%7}, {%8,%9}, {%0,%1,%2,%3};"
        : "+f"(d[0]), "+f"(d[1]), "+f"(d[2]), "+f"(d[3])
        : "r"(a[0]), "r"(a[1]), "r"(a[2]), "r"(a[3]), "r"(b[0]), "r"(b[1]));
}

#define SMEM_SWIZZLE_128B(o) ((o) ^ (((o) >> 3) & 0x70))

// bf16 hi/lo split of two floats -> packed bf16x2 words
__device__ __forceinline__ void split2(float x, float y,
                                       unsigned& hpack, unsigned& lpack) {
    unsigned h;
    asm("cvt.rn.satfinite.bf16x2.f32 %0, %1, %2;" : "=r"(h) : "f"(y), "f"(x));
    float hx = __uint_as_float(h << 16);
    float hy = __uint_as_float(h & 0xFFFF0000u);
    unsigned l;
    float rx = x - hx, ry = y - hy;
    asm("cvt.rn.satfinite.bf16x2.f32 %0, %1, %2;" : "=r"(l) : "f"(ry), "f"(rx));
    hpack = h; lpack = l;
}

// ------------- smem layout (dynamic): 2 buf x 4 tiles x 16KB ----------------
#define TILE_B   (128 * TK_ * 2)                 /* 16384 bytes */
#define OFF_AH(b) ((b) * (4 * TILE_B) + 0 * TILE_B)
#define OFF_AL(b) ((b) * (4 * TILE_B) + 1 * TILE_B)
#define OFF_BH(b) ((b) * (4 * TILE_B) + 2 * TILE_B)
#define OFF_BL(b) ((b) * (4 * TILE_B) + 3 * TILE_B)
#define SMEM_BYTES (8 * TILE_B)                  /* 131072 */

// ------------- Kernel 0: split X^T into bf16 hi/lo --------------------------
__global__ void xsplit_kernel(const float* __restrict__ inputs) {
    int idx = blockIdx.x * blockDim.x + threadIdx.x;   // j*N_ + m
    if (idx >= BD_ * N_) return;
    int j = idx / N_;          // col = b*16 + d
    int m = idx % N_;
    int b = j >> 4, d = j & 15;
    float x = inputs[((size_t)b * N_ + m) * D_ + d];
    __nv_bfloat16 h = __float2bfloat16_rn(x);
    float r = x - __bfloat162float(h);
    g_Xh[idx] = h;
    g_Xl[idx] = __float2bfloat16_rn(r);
}

// ------------- Kernel 1: bf16-split GEMM via mma.sync -----------------------
// Block: C[128,128] tile of Y_k = sup_k @ X. grid = (48, 3). 512 threads.
// 16 warps in a 4x4 grid; warp tile 32x32 (2 m-tiles x 4 n-tiles).
__global__ __launch_bounds__(512, 1)
void gemm_mma_kernel(const float* __restrict__ supports) {
    extern __shared__ char smem_raw[];
    const unsigned sbase = smem_u32(smem_raw);

    const int t    = threadIdx.x;
    const int wid  = t >> 5;
    const int lane = t & 31;
    const int row0 = blockIdx.x * 128;

    const float* A = supports + (size_t)blockIdx.y * N_ * N_;
    float*       C = g_Y      + (size_t)blockIdx.y * N_ * BD_;

    // warp tile origin within the 128x128 block tile
    const int wm0 = (wid >> 2) * 32;    // 0,32,64,96
    const int wn0 = (wid & 3) * 32;     // 0,32,64,96

    // loader mapping (A): 16 threads per row, float4 each, 4 row-passes
    const int a_sub = t >> 4;           // 0..31
    const int a_c4  = (t & 15) << 2;    // float col 0,4,...,60

    // ldmatrix lane address components (element coords within tile)
    const int a_r  = lane & 15;               // row within 16-row A frag
    const int a_k8 = (lane >> 4) << 3;        // 0 or 8 (k offset)
    const int b_n  = ((lane >> 4) << 3) + (lane & 7);  // 0..15 within 16-n group
    const int b_k8 = ((lane >> 3) & 1) << 3;  // 0 or 8

    float acc[2][4][4];
    #pragma unroll
    for (int i = 0; i < 2; ++i)
        #pragma unroll
        for (int j = 0; j < 4; ++j)
            #pragma unroll
            for (int p = 0; p < 4; ++p) acc[i][j][p] = 0.f;

    float4 av[4];

    // ---- prologue: A(kt=0) regs + B(kt=0) cp.async, convert+STS A into buf0
    #pragma unroll
    for (int p = 0; p < 4; ++p)
        av[p] = __ldg(reinterpret_cast<const float4*>(
            &A[(size_t)(row0 + p * 32 + a_sub) * N_ + a_c4]));
    #pragma unroll
    for (int i = 0; i < 2; ++i) {
        const int c   = t + i * 512;          // 16B chunk (0..1023)
        const int r   = c >> 3;               // B row (n col) 0..127
        const int kin = (c & 7) << 3;         // bf16 k within tile
        const unsigned swz = SMEM_SWIZZLE_128B((unsigned)(c << 4));
        cp_async16(sbase + OFF_BH(0) + swz, &g_Xh[(size_t)r * N_ + kin]);
        cp_async16(sbase + OFF_BL(0) + swz, &g_Xl[(size_t)r * N_ + kin]);
    }
    cp_commit();
    #pragma unroll
    for (int p = 0; p < 4; ++p) {
        const int row = p * 32 + a_sub;
        const unsigned boff = (unsigned)(row * 128 + (a_c4 << 1));
        const unsigned swz  = SMEM_SWIZZLE_128B(boff);
        unsigned h01, l01, h23, l23;
        split2(av[p].x, av[p].y, h01, l01);
        split2(av[p].z, av[p].w, h23, l23);
        sts64(sbase + OFF_AH(0) + swz, ((unsigned long long)h23 << 32) | h01);
        sts64(sbase + OFF_AL(0) + swz, ((unsigned long long)l23 << 32) | l01);
    }

    for (int kt = 0; kt < NSTEP_; ++kt) {
        const int buf  = kt & 1;
        const int nbuf = buf ^ 1;

        cp_wait<0>();
        __syncthreads();   // buf tiles (cp.async B + STS A) visible; prior compute done

        // issue loads for kt+1 into nbuf (overlap with compute below)
        if (kt + 1 < NSTEP_) {
            const int kk2 = (kt + 1) * TK_;
            #pragma unroll
            for (int p = 0; p < 4; ++p)
                av[p] = __ldg(reinterpret_cast<const float4*>(
                    &A[(size_t)(row0 + p * 32 + a_sub) * N_ + kk2 + a_c4]));
            #pragma unroll
            for (int i = 0; i < 2; ++i) {
                const int c   = t + i * 512;
                const int r   = c >> 3;
                const int kin = (c & 7) << 3;
                const unsigned swz = SMEM_SWIZZLE_128B((unsigned)(c << 4));
                cp_async16(sbase + OFF_BH(nbuf) + swz, &g_Xh[(size_t)r * N_ + kk2 + kin]);
                cp_async16(sbase + OFF_BL(nbuf) + swz, &g_Xl[(size_t)r * N_ + kk2 + kin]);
            }
            cp_commit();
        }

        // ---- compute on buf: 4 k16 steps, 3 independent MMA passes each
        const unsigned ah_base = sbase + OFF_AH(buf);
        const unsigned al_base = sbase + OFF_AL(buf);
        const unsigned bh_base = sbase + OFF_BH(buf);
        const unsigned bl_base = sbase + OFF_BL(buf);

        #pragma unroll
        for (int ks = 0; ks < 4; ++ks) {
            const int kk16 = ks * 16;

            unsigned ah[2][4], al[2][4];
            #pragma unroll
            for (int mt = 0; mt < 2; ++mt) {
                const unsigned off = SMEM_SWIZZLE_128B(
                    (unsigned)((wm0 + mt * 16 + a_r) * 128 + (kk16 + a_k8) * 2));
                ldsm_x4(ah[mt][0], ah[mt][1], ah[mt][2], ah[mt][3], ah_base + off);
                ldsm_x4(al[mt][0], al[mt][1], al[mt][2], al[mt][3], al_base + off);
            }
            unsigned bh[4][2], bl[4][2];
            #pragma unroll
            for (int np = 0; np < 2; ++np) {   // each x4 covers two n-tiles
                const unsigned off = SMEM_SWIZZLE_128B(
                    (unsigned)((wn0 + np * 16 + b_n) * 128 + (kk16 + b_k8) * 2));
                ldsm_x4(bh[np*2][0], bh[np*2][1], bh[np*2+1][0], bh[np*2+1][1],
                        bh_base + off);
                ldsm_x4(bl[np*2][0], bl[np*2][1], bl[np*2+1][0], bl[np*2+1][1],
                        bl_base + off);
            }
            // pass 1: hi*hi — 8 independent accumulators
            #pragma unroll
            for (int mt = 0; mt < 2; ++mt)
                #pragma unroll
                for (int nt = 0; nt < 4; ++nt)
                    mma16816(acc[mt][nt], ah[mt], bh[nt]);
            // pass 2: hi*lo
            #pragma unroll
            for (int mt = 0; mt < 2; ++mt)
                #pragma unroll
                for (int nt = 0; nt < 4; ++nt)
                    mma16816(acc[mt][nt], ah[mt], bl[nt]);
            // pass 3: lo*hi
            #pragma unroll
            for (int mt = 0; mt < 2; ++mt)
                #pragma unroll
                for (int nt = 0; nt < 4; ++nt)
                    mma16816(acc[mt][nt], al[mt], bh[nt]);
        }

        // convert prefetched A regs -> bf16 hi/lo into nbuf
        if (kt + 1 < NSTEP_) {
            #pragma unroll
            for (int p = 0; p < 4; ++p) {
                const int row = p * 32 + a_sub;
                const unsigned boff = (unsigned)(row * 128 + (a_c4 << 1));
                const unsigned swz  = SMEM_SWIZZLE_128B(boff);
                unsigned h01, l01, h23, l23;
                split2(av[p].x, av[p].y, h01, l01);
                split2(av[p].z, av[p].w, h23, l23);
                sts64(sbase + OFF_AH(nbuf) + swz, ((unsigned long long)h23 << 32) | h01);
                sts64(sbase + OFF_AL(nbuf) + swz, ((unsigned long long)l23 << 32) | l01);
            }
        }
    }

    // ---- epilogue: write accumulators to g_Y (fp32)
    const int lr = lane >> 2;          // 0..7
    const int lc = (lane & 3) << 1;    // 0,2,4,6
    #pragma unroll
    for (int mt = 0; mt < 2; ++mt) {
        #pragma unroll
        for (int nt = 0; nt < 4; ++nt) {
            const int m = row0 + wm0 + mt * 16 + lr;
            const int n = wn0 + nt * 8 + lc;
            float2 v0 = make_float2(acc[mt][nt][0], acc[mt][nt][1]);
            float2 v1 = make_float2(acc[mt][nt][2], acc[mt][nt][3]);
            *reinterpret_cast<float2*>(&C[(size_t)m * BD_ + n])       = v0;
            *reinterpret_cast<float2*>(&C[(size_t)(m + 8) * BD_ + n]) = v1;
        }
    }
}

// ------------- Kernel 2: out = (Y + I-term) @ W^T + b ----------------------
__global__ __launch_bounds__(256)
void out_kernel(const float* __restrict__ inputs,
                const float* __restrict__ W,
                const float* __restrict__ bias,
                float* __restrict__ out) {
    __shared__ float Ysh[32][49];
    __shared__ float Wsh[64][49];
    __shared__ float Bsh[64];

    const int b  = blockIdx.y;
    const int n0 = blockIdx.x * 32;
    const int t  = threadIdx.x;

    for (int idx = t; idx < 64 * 48; idx += 256)
        Wsh[idx / 48][idx % 48] = W[idx];
    if (t < 64) Bsh[t] = bias[t];

    for (int idx = t; idx < 32 * 48; idx += 256) {
        const int nn = idx / 48;
        const int j  = idx % 48;        // feature index d*3 + k
        const int d  = j / 3;
        const int kk = j % 3;
        const int n  = n0 + nn;
        Ysh[nn][j] = g_Y[(size_t)kk * N_ * BD_ + (size_t)n * BD_ + b * 16 + d]
                   + inputs[((size_t)b * N_ + n) * D_ + d];
    }
    __syncthreads();

    const int o  = t & 63;
    const int ng = t >> 6;
    #pragma unroll
    for (int r = 0; r < 8; ++r) {
        const int nn = ng * 8 + r;
        float acc = Bsh[o];
        #pragma unroll
        for (int j = 0; j < 48; ++j)
            acc += Ysh[nn][j] * Wsh[o][j];
        out[((size_t)b * N_ + n0 + nn) * O_ + o] = acc;
    }
}

// ------------- launch -------------------------------------------------------
extern "C" void kernel_launch(void* const* d_in, const int* in_sizes, int n_in,
                              void* d_out, int out_size) {
    const float* inputs = nullptr;
    const float* supports = nullptr;
    const float* W = nullptr;
    const float* bias = nullptr;
    for (int i = 0; i < n_in; ++i) {
        if      (in_sizes[i] == B_ * N_ * D_) inputs   = (const float*)d_in[i];
        else if (in_sizes[i] == K_ * N_ * N_) supports = (const float*)d_in[i];
        else if (in_sizes[i] == O_ * D_ * K_) W        = (const float*)d_in[i];
        else if (in_sizes[i] == O_)           bias     = (const float*)d_in[i];
    }
    float* out = (float*)d_out;

    cudaFuncSetAttribute(gemm_mma_kernel,
                         cudaFuncAttributeMaxDynamicSharedMemorySize, SMEM_BYTES);

    xsplit_kernel<<<(BD_ * N_ + 255) / 256, 256>>>(inputs);
    gemm_mma_kernel<<<dim3(N_ / 128, K_), 512, SMEM_BYTES>>>(supports);
    out_kernel<<<dim3(N_ / 32, B_), 256>>>(inputs, W, bias, out);
}

// round 7
// speedup vs baseline: 3.9031x; 1.6753x over previous
#include <cuda_runtime.h>
#include <cuda_fp16.h>
#include <cstdint>

// Problem constants
#define B_  8
#define N_  6144
#define D_  16
#define K_  3
#define O_  64
#define BD_ 128            // B*D columns
#define TK_ 64             // k-tile (64 fp16 = 128B row)
#define NSTEP_ (N_ / TK_)  // 96

// ------------- global scratch (no cudaMalloc allowed) ----------------------
__device__ __half g_Xf[(size_t)BD_ * N_];          // X^T fp16 [col j][k]
__device__ float  g_Y [(size_t)K_ * N_ * BD_];

// ------------- PTX helpers --------------------------------------------------
__device__ __forceinline__ unsigned smem_u32(const void* p) {
    return (unsigned)__cvta_generic_to_shared(p);
}
__device__ __forceinline__ void cp_async16(unsigned dst, const void* gsrc) {
    asm volatile("cp.async.cg.shared.global [%0], [%1], 16;\n" :: "r"(dst), "l"(gsrc));
}
__device__ __forceinline__ void cp_commit() {
    asm volatile("cp.async.commit_group;\n" ::: "memory");
}
template<int NW> __device__ __forceinline__ void cp_wait() {
    asm volatile("cp.async.wait_group %0;\n" :: "n"(NW) : "memory");
}
__device__ __forceinline__ void sts64(unsigned addr, unsigned long long v) {
    asm volatile("st.shared.b64 [%0], %1;" :: "r"(addr), "l"(v) : "memory");
}
__device__ __forceinline__ void ldsm_x4(unsigned& r0, unsigned& r1,
                                        unsigned& r2, unsigned& r3, unsigned addr) {
    asm volatile("ldmatrix.sync.aligned.m8n8.x4.shared.b16 {%0,%1,%2,%3}, [%4];"
                 : "=r"(r0), "=r"(r1), "=r"(r2), "=r"(r3) : "r"(addr));
}
// D(f32) += A(f16) * B(f16), m16n8k16, row.col
__device__ __forceinline__ void mma16816(float* d, const unsigned* a,
                                         const unsigned* b) {
    asm volatile(
        "mma.sync.aligned.m16n8k16.row.col.f32.f16.f16.f32 "
        "{%0,%1,%2,%3}, {%4,%5,%6,%7}, {%8,%9}, {%0,%1,%2,%3};"
        : "+f"(d[0]), "+f"(d[1]), "+f"(d[2]), "+f"(d[3])
        : "r"(a[0]), "r"(a[1]), "r"(a[2]), "r"(a[3]), "r"(b[0]), "r"(b[1]));
}

#define SMEM_SWIZZLE_128B(o) ((o) ^ (((o) >> 3) & 0x70))

// pack two floats -> fp16x2 (lo = x, hi = y)
__device__ __forceinline__ unsigned cvt_f16x2(float x, float y) {
    unsigned r;
    asm("cvt.rn.f16x2.f32 %0, %1, %2;" : "=r"(r) : "f"(y), "f"(x));
    return r;
}

// ------------- smem layout (dynamic): 2 buf x 2 tiles x 16KB ----------------
#define TILE_B   (128 * TK_ * 2)                 /* 16384 bytes */
#define OFF_A(b) ((b) * (2 * TILE_B) + 0 * TILE_B)
#define OFF_B(b) ((b) * (2 * TILE_B) + 1 * TILE_B)
#define SMEM_BYTES (4 * TILE_B)                  /* 65536 */

// ------------- Kernel 0: X^T -> fp16 ----------------------------------------
__global__ void xsplit_kernel(const float* __restrict__ inputs) {
    int idx = blockIdx.x * blockDim.x + threadIdx.x;   // j*N_ + m
    if (idx >= BD_ * N_) return;
    int j = idx / N_;          // col = b*16 + d
    int m = idx % N_;
    int b = j >> 4, d = j & 15;
    float x = inputs[((size_t)b * N_ + m) * D_ + d];
    g_Xf[idx] = __float2half_rn(x);
}

// ------------- Kernel 1: fp16 GEMM via mma.sync -----------------------------
// Block: C[128,128] tile of Y_k = sup_k @ X. grid = (48, 3). 512 threads.
// 16 warps in a 4x4 grid; warp tile 32x32 (2 m-tiles x 4 n-tiles).
__global__ __launch_bounds__(512, 1)
void gemm_mma_kernel(const float* __restrict__ supports) {
    extern __shared__ char smem_raw[];
    const unsigned sbase = smem_u32(smem_raw);

    const int t    = threadIdx.x;
    const int wid  = t >> 5;
    const int lane = t & 31;
    const int row0 = blockIdx.x * 128;

    const float* A = supports + (size_t)blockIdx.y * N_ * N_;
    float*       C = g_Y      + (size_t)blockIdx.y * N_ * BD_;

    // warp tile origin within the 128x128 block tile
    const int wm0 = (wid >> 2) * 32;    // 0,32,64,96
    const int wn0 = (wid & 3) * 32;     // 0,32,64,96

    // loader mapping (A): 16 threads per row, float4 each, 4 row-passes
    const int a_sub = t >> 4;           // 0..31
    const int a_c4  = (t & 15) << 2;    // float col 0,4,...,60

    // ldmatrix lane address components
    const int a_r  = lane & 15;               // row within 16-row A frag
    const int a_k8 = (lane >> 4) << 3;        // 0 or 8 (k offset)
    const int b_n  = ((lane >> 4) << 3) + (lane & 7);  // 0..15 within 16-n group
    const int b_k8 = ((lane >> 3) & 1) << 3;  // 0 or 8

    float acc[2][4][4];
    #pragma unroll
    for (int i = 0; i < 2; ++i)
        #pragma unroll
        for (int j = 0; j < 4; ++j)
            #pragma unroll
            for (int p = 0; p < 4; ++p) acc[i][j][p] = 0.f;

    float4 av[4];

    // ---- prologue: A(kt=0) regs + B(kt=0) cp.async, convert+STS A into buf0
    #pragma unroll
    for (int p = 0; p < 4; ++p)
        av[p] = __ldg(reinterpret_cast<const float4*>(
            &A[(size_t)(row0 + p * 32 + a_sub) * N_ + a_c4]));
    {
        const int c   = t;                    // 16B chunk (0..511 -> half of 1024)
        const int r   = c >> 3;               // B row 0..63  (first pass)
        const int kin = (c & 7) << 3;
        const unsigned swz  = SMEM_SWIZZLE_128B((unsigned)(c << 4));
        cp_async16(sbase + OFF_B(0) + swz, &g_Xf[(size_t)r * N_ + kin]);
        const int c2   = t + 512;
        const int r2   = c2 >> 3;
        const int kin2 = (c2 & 7) << 3;
        const unsigned swz2 = SMEM_SWIZZLE_128B((unsigned)(c2 << 4));
        cp_async16(sbase + OFF_B(0) + swz2, &g_Xf[(size_t)r2 * N_ + kin2]);
    }
    cp_commit();
    #pragma unroll
    for (int p = 0; p < 4; ++p) {
        const int row = p * 32 + a_sub;
        const unsigned boff = (unsigned)(row * 128 + (a_c4 << 1));
        const unsigned swz  = SMEM_SWIZZLE_128B(boff);
        unsigned h01 = cvt_f16x2(av[p].x, av[p].y);
        unsigned h23 = cvt_f16x2(av[p].z, av[p].w);
        sts64(sbase + OFF_A(0) + swz, ((unsigned long long)h23 << 32) | h01);
    }

    for (int kt = 0; kt < NSTEP_; ++kt) {
        const int buf  = kt & 1;
        const int nbuf = buf ^ 1;

        cp_wait<0>();
        __syncthreads();   // buf tiles visible; prior compute done

        // issue loads for kt+1 into nbuf (overlap with compute below)
        if (kt + 1 < NSTEP_) {
            const int kk2 = (kt + 1) * TK_;
            #pragma unroll
            for (int p = 0; p < 4; ++p)
                av[p] = __ldg(reinterpret_cast<const float4*>(
                    &A[(size_t)(row0 + p * 32 + a_sub) * N_ + kk2 + a_c4]));
            {
                const int c   = t;
                const int r   = c >> 3;
                const int kin = (c & 7) << 3;
                const unsigned swz  = SMEM_SWIZZLE_128B((unsigned)(c << 4));
                cp_async16(sbase + OFF_B(nbuf) + swz,
                           &g_Xf[(size_t)r * N_ + kk2 + kin]);
                const int c2   = t + 512;
                const int r2   = c2 >> 3;
                const int kin2 = (c2 & 7) << 3;
                const unsigned swz2 = SMEM_SWIZZLE_128B((unsigned)(c2 << 4));
                cp_async16(sbase + OFF_B(nbuf) + swz2,
                           &g_Xf[(size_t)r2 * N_ + kk2 + kin2]);
            }
            cp_commit();
        }

        // ---- compute on buf: 4 k16 steps, 8 MMAs each
        const unsigned a_base = sbase + OFF_A(buf);
        const unsigned b_base = sbase + OFF_B(buf);

        #pragma unroll
        for (int ks = 0; ks < 4; ++ks) {
            const int kk16 = ks * 16;

            unsigned af[2][4];
            #pragma unroll
            for (int mt = 0; mt < 2; ++mt) {
                const unsigned off = SMEM_SWIZZLE_128B(
                    (unsigned)((wm0 + mt * 16 + a_r) * 128 + (kk16 + a_k8) * 2));
                ldsm_x4(af[mt][0], af[mt][1], af[mt][2], af[mt][3], a_base + off);
            }
            unsigned bf[4][2];
            #pragma unroll
            for (int np = 0; np < 2; ++np) {   // each x4 covers two n-tiles
                const unsigned off = SMEM_SWIZZLE_128B(
                    (unsigned)((wn0 + np * 16 + b_n) * 128 + (kk16 + b_k8) * 2));
                ldsm_x4(bf[np*2][0], bf[np*2][1], bf[np*2+1][0], bf[np*2+1][1],
                        b_base + off);
            }
            #pragma unroll
            for (int mt = 0; mt < 2; ++mt)
                #pragma unroll
                for (int nt = 0; nt < 4; ++nt)
                    mma16816(acc[mt][nt], af[mt], bf[nt]);
        }

        // convert prefetched A regs -> fp16 into nbuf
        if (kt + 1 < NSTEP_) {
            #pragma unroll
            for (int p = 0; p < 4; ++p) {
                const int row = p * 32 + a_sub;
                const unsigned boff = (unsigned)(row * 128 + (a_c4 << 1));
                const unsigned swz  = SMEM_SWIZZLE_128B(boff);
                unsigned h01 = cvt_f16x2(av[p].x, av[p].y);
                unsigned h23 = cvt_f16x2(av[p].z, av[p].w);
                sts64(sbase + OFF_A(nbuf) + swz,
                      ((unsigned long long)h23 << 32) | h01);
            }
        }
    }

    // ---- epilogue: write accumulators to g_Y (fp32)
    const int lr = lane >> 2;          // 0..7
    const int lc = (lane & 3) << 1;    // 0,2,4,6
    #pragma unroll
    for (int mt = 0; mt < 2; ++mt) {
        #pragma unroll
        for (int nt = 0; nt < 4; ++nt) {
            const int m = row0 + wm0 + mt * 16 + lr;
            const int n = wn0 + nt * 8 + lc;
            float2 v0 = make_float2(acc[mt][nt][0], acc[mt][nt][1]);
            float2 v1 = make_float2(acc[mt][nt][2], acc[mt][nt][3]);
            *reinterpret_cast<float2*>(&C[(size_t)m * BD_ + n])       = v0;
            *reinterpret_cast<float2*>(&C[(size_t)(m + 8) * BD_ + n]) = v1;
        }
    }
}

// ------------- Kernel 2: out = (Y + I-term) @ W^T + b ----------------------
__global__ __launch_bounds__(256)
void out_kernel(const float* __restrict__ inputs,
                const float* __restrict__ W,
                const float* __restrict__ bias,
                float* __restrict__ out) {
    __shared__ float Ysh[32][49];
    __shared__ float Wsh[64][49];
    __shared__ float Bsh[64];

    const int b  = blockIdx.y;
    const int n0 = blockIdx.x * 32;
    const int t  = threadIdx.x;

    for (int idx = t; idx < 64 * 48; idx += 256)
        Wsh[idx / 48][idx % 48] = W[idx];
    if (t < 64) Bsh[t] = bias[t];

    for (int idx = t; idx < 32 * 48; idx += 256) {
        const int nn = idx / 48;
        const int j  = idx % 48;        // feature index d*3 + k
        const int d  = j / 3;
        const int kk = j % 3;
        const int n  = n0 + nn;
        Ysh[nn][j] = g_Y[(size_t)kk * N_ * BD_ + (size_t)n * BD_ + b * 16 + d]
                   + inputs[((size_t)b * N_ + n) * D_ + d];
    }
    __syncthreads();

    const int o  = t & 63;
    const int ng = t >> 6;
    #pragma unroll
    for (int r = 0; r < 8; ++r) {
        const int nn = ng * 8 + r;
        float acc = Bsh[o];
        #pragma unroll
        for (int j = 0; j < 48; ++j)
            acc += Ysh[nn][j] * Wsh[o][j];
        out[((size_t)b * N_ + n0 + nn) * O_ + o] = acc;
    }
}

// ------------- launch -------------------------------------------------------
extern "C" void kernel_launch(void* const* d_in, const int* in_sizes, int n_in,
                              void* d_out, int out_size) {
    const float* inputs = nullptr;
    const float* supports = nullptr;
    const float* W = nullptr;
    const float* bias = nullptr;
    for (int i = 0; i < n_in; ++i) {
        if      (in_sizes[i] == B_ * N_ * D_) inputs   = (const float*)d_in[i];
        else if (in_sizes[i] == K_ * N_ * N_) supports = (const float*)d_in[i];
        else if (in_sizes[i] == O_ * D_ * K_) W        = (const float*)d_in[i];
        else if (in_sizes[i] == O_)           bias     = (const float*)d_in[i];
    }
    float* out = (float*)d_out;

    cudaFuncSetAttribute(gemm_mma_kernel,
                         cudaFuncAttributeMaxDynamicSharedMemorySize, SMEM_BYTES);

    xsplit_kernel<<<(BD_ * N_ + 255) / 256, 256>>>(inputs);
    gemm_mma_kernel<<<dim3(N_ / 128, K_), 512, SMEM_BYTES>>>(supports);
    out_kernel<<<dim3(N_ / 32, B_), 256>>>(inputs, W, bias, out);
}

// round 8
// speedup vs baseline: 4.3344x; 1.1105x over previous
#include <cuda_runtime.h>
#include <cuda_fp16.h>
#include <cstdint>

// Problem constants
#define B_  8
#define N_  6144
#define D_  16
#define K_  3
#define O_  64
#define BD_ 128             // B*D columns
#define TK2_ 128            // k-tile (two 64-wide subtiles)
#define NSTEP2_ (N_ / TK2_) // 48

// ------------- global scratch (no cudaMalloc allowed) ----------------------
__device__ __half g_Xf[(size_t)BD_ * N_];          // X^T fp16 [col j][k]
__device__ float  g_Y [(size_t)K_ * N_ * BD_];

// ------------- PTX helpers --------------------------------------------------
__device__ __forceinline__ unsigned smem_u32(const void* p) {
    return (unsigned)__cvta_generic_to_shared(p);
}
__device__ __forceinline__ void cp_async16(unsigned dst, const void* gsrc) {
    asm volatile("cp.async.cg.shared.global [%0], [%1], 16;\n" :: "r"(dst), "l"(gsrc));
}
__device__ __forceinline__ void cp_commit() {
    asm volatile("cp.async.commit_group;\n" ::: "memory");
}
template<int NW> __device__ __forceinline__ void cp_wait() {
    asm volatile("cp.async.wait_group %0;\n" :: "n"(NW) : "memory");
}
__device__ __forceinline__ void sts64(unsigned addr, unsigned long long v) {
    asm volatile("st.shared.b64 [%0], %1;" :: "r"(addr), "l"(v) : "memory");
}
__device__ __forceinline__ void ldsm_x4(unsigned& r0, unsigned& r1,
                                        unsigned& r2, unsigned& r3, unsigned addr) {
    asm volatile("ldmatrix.sync.aligned.m8n8.x4.shared.b16 {%0,%1,%2,%3}, [%4];"
                 : "=r"(r0), "=r"(r1), "=r"(r2), "=r"(r3) : "r"(addr));
}
// D(f32) += A(f16) * B(f16), m16n8k16, row.col
__device__ __forceinline__ void mma16816(float* d, const unsigned* a,
                                         const unsigned* b) {
    asm volatile(
        "mma.sync.aligned.m16n8k16.row.col.f32.f16.f16.f32 "
        "{%0,%1,%2,%3}, {%4,%5,%6,%7}, {%8,%9}, {%0,%1,%2,%3};"
        : "+f"(d[0]), "+f"(d[1]), "+f"(d[2]), "+f"(d[3])
        : "r"(a[0]), "r"(a[1]), "r"(a[2]), "r"(a[3]), "r"(b[0]), "r"(b[1]));
}

#define SMEM_SWIZZLE_128B(o) ((o) ^ (((o) >> 3) & 0x70))

// pack two floats -> fp16x2 (lo = x, hi = y)
__device__ __forceinline__ unsigned cvt_f16x2(float x, float y) {
    unsigned r;
    asm("cvt.rn.f16x2.f32 %0, %1, %2;" : "=r"(r) : "f"(y), "f"(x));
    return r;
}

// ------------- smem layout: 2 buf x (A0 A1 B0 B1) x 16KB --------------------
#define SUB_B     16384
#define OFF_A(buf,h)  ((buf) * 65536 + (h) * SUB_B)
#define OFF_Bt(buf,h) ((buf) * 65536 + 32768 + (h) * SUB_B)
#define SMEM_BYTES 131072

// ------------- Kernel 0: X^T -> fp16 ----------------------------------------
__global__ void xsplit_kernel(const float* __restrict__ inputs) {
    int idx = blockIdx.x * blockDim.x + threadIdx.x;   // j*N_ + m
    if (idx >= BD_ * N_) return;
    int j = idx / N_;          // col = b*16 + d
    int m = idx % N_;
    int b = j >> 4, d = j & 15;
    float x = inputs[((size_t)b * N_ + m) * D_ + d];
    g_Xf[idx] = __float2half_rn(x);
}

// ------------- Kernel 1: fp16 GEMM via mma.sync, TK=128 ---------------------
// Block: C[128,128] tile of Y_k = sup_k @ X. grid = (48, 3). 512 threads.
// 16 warps in a 4x4 grid; warp tile 32x32 (2 m-tiles x 4 n-tiles).
__global__ __launch_bounds__(512, 1)
void gemm_mma_kernel(const float* __restrict__ supports) {
    extern __shared__ char smem_raw[];
    const unsigned sbase = smem_u32(smem_raw);

    const int t    = threadIdx.x;
    const int wid  = t >> 5;
    const int lane = t & 31;
    const int row0 = blockIdx.x * 128;

    const float* A = supports + (size_t)blockIdx.y * N_ * N_;
    float*       C = g_Y      + (size_t)blockIdx.y * N_ * BD_;

    const int wm0 = (wid >> 2) * 32;    // 0,32,64,96
    const int wn0 = (wid & 3) * 32;     // 0,32,64,96

    // loader mapping (A): 16 threads per row, float4 each
    const int a_sub = t >> 4;           // 0..31
    const int a_c4  = (t & 15) << 2;    // float col 0,4,...,60 within subtile

    // ldmatrix lane address components
    const int a_r  = lane & 15;
    const int a_k8 = (lane >> 4) << 3;
    const int b_n  = ((lane >> 4) << 3) + (lane & 7);
    const int b_k8 = ((lane >> 3) & 1) << 3;

    float acc[2][4][4];
    #pragma unroll
    for (int i = 0; i < 2; ++i)
        #pragma unroll
        for (int j = 0; j < 4; ++j)
            #pragma unroll
            for (int p = 0; p < 4; ++p) acc[i][j][p] = 0.f;

    float4 av[8];   // 8 float4: [h(2)][rowpass(4)]

    // ---- prologue: A(kt=0) regs + B(kt=0) cp.async, convert+STS into buf0
    #pragma unroll
    for (int p = 0; p < 8; ++p) {
        const int h   = p >> 2;
        const int row = (p & 3) * 32 + a_sub;
        av[p] = __ldg(reinterpret_cast<const float4*>(
            &A[(size_t)(row0 + row) * N_ + h * 64 + a_c4]));
    }
    #pragma unroll
    for (int h = 0; h < 2; ++h)
        #pragma unroll
        for (int j = 0; j < 2; ++j) {
            const int c   = t + j * 512;       // 16B chunk (0..1023)
            const int r   = c >> 3;            // B row (n col) 0..127
            const int kin = (c & 7) << 3;
            const unsigned swz = SMEM_SWIZZLE_128B((unsigned)(c << 4));
            cp_async16(sbase + OFF_Bt(0, h) + swz,
                       &g_Xf[(size_t)r * N_ + h * 64 + kin]);
        }
    cp_commit();
    #pragma unroll
    for (int p = 0; p < 8; ++p) {
        const int h   = p >> 2;
        const int row = (p & 3) * 32 + a_sub;
        const unsigned boff = (unsigned)(row * 128 + (a_c4 << 1));
        const unsigned swz  = SMEM_SWIZZLE_128B(boff);
        unsigned h01 = cvt_f16x2(av[p].x, av[p].y);
        unsigned h23 = cvt_f16x2(av[p].z, av[p].w);
        sts64(sbase + OFF_A(0, h) + swz, ((unsigned long long)h23 << 32) | h01);
    }

    for (int kt = 0; kt < NSTEP2_; ++kt) {
        const int buf  = kt & 1;
        const int nbuf = buf ^ 1;

        cp_wait<0>();
        __syncthreads();   // buf tiles visible; prior compute done

        // issue loads for kt+1 into nbuf (overlap with compute below)
        if (kt + 1 < NSTEP2_) {
            const int kk2 = (kt + 1) * TK2_;
            #pragma unroll
            for (int p = 0; p < 8; ++p) {
                const int h   = p >> 2;
                const int row = (p & 3) * 32 + a_sub;
                av[p] = __ldg(reinterpret_cast<const float4*>(
                    &A[(size_t)(row0 + row) * N_ + kk2 + h * 64 + a_c4]));
            }
            #pragma unroll
            for (int h = 0; h < 2; ++h)
                #pragma unroll
                for (int j = 0; j < 2; ++j) {
                    const int c   = t + j * 512;
                    const int r   = c >> 3;
                    const int kin = (c & 7) << 3;
                    const unsigned swz = SMEM_SWIZZLE_128B((unsigned)(c << 4));
                    cp_async16(sbase + OFF_Bt(nbuf, h) + swz,
                               &g_Xf[(size_t)r * N_ + kk2 + h * 64 + kin]);
                }
            cp_commit();
        }

        // ---- compute on buf: 8 k16 steps (2 subtiles x 4), 8 MMAs each
        #pragma unroll
        for (int ks = 0; ks < 8; ++ks) {
            const int h    = ks >> 2;
            const int kk16 = (ks & 3) * 16;
            const unsigned a_base = sbase + OFF_A(buf, h);
            const unsigned b_base = sbase + OFF_Bt(buf, h);

            unsigned af[2][4];
            #pragma unroll
            for (int mt = 0; mt < 2; ++mt) {
                const unsigned off = SMEM_SWIZZLE_128B(
                    (unsigned)((wm0 + mt * 16 + a_r) * 128 + (kk16 + a_k8) * 2));
                ldsm_x4(af[mt][0], af[mt][1], af[mt][2], af[mt][3], a_base + off);
            }
            unsigned bf[4][2];
            #pragma unroll
            for (int np = 0; np < 2; ++np) {
                const unsigned off = SMEM_SWIZZLE_128B(
                    (unsigned)((wn0 + np * 16 + b_n) * 128 + (kk16 + b_k8) * 2));
                ldsm_x4(bf[np*2][0], bf[np*2][1], bf[np*2+1][0], bf[np*2+1][1],
                        b_base + off);
            }
            #pragma unroll
            for (int mt = 0; mt < 2; ++mt)
                #pragma unroll
                for (int nt = 0; nt < 4; ++nt)
                    mma16816(acc[mt][nt], af[mt], bf[nt]);
        }

        // convert prefetched A regs -> fp16 into nbuf
        if (kt + 1 < NSTEP2_) {
            #pragma unroll
            for (int p = 0; p < 8; ++p) {
                const int h   = p >> 2;
                const int row = (p & 3) * 32 + a_sub;
                const unsigned boff = (unsigned)(row * 128 + (a_c4 << 1));
                const unsigned swz  = SMEM_SWIZZLE_128B(boff);
                unsigned h01 = cvt_f16x2(av[p].x, av[p].y);
                unsigned h23 = cvt_f16x2(av[p].z, av[p].w);
                sts64(sbase + OFF_A(nbuf, h) + swz,
                      ((unsigned long long)h23 << 32) | h01);
            }
        }
    }

    // ---- epilogue: write accumulators to g_Y (fp32)
    const int lr = lane >> 2;
    const int lc = (lane & 3) << 1;
    #pragma unroll
    for (int mt = 0; mt < 2; ++mt) {
        #pragma unroll
        for (int nt = 0; nt < 4; ++nt) {
            const int m = row0 + wm0 + mt * 16 + lr;
            const int n = wn0 + nt * 8 + lc;
            float2 v0 = make_float2(acc[mt][nt][0], acc[mt][nt][1]);
            float2 v1 = make_float2(acc[mt][nt][2], acc[mt][nt][3]);
            *reinterpret_cast<float2*>(&C[(size_t)m * BD_ + n])       = v0;
            *reinterpret_cast<float2*>(&C[(size_t)(m + 8) * BD_ + n]) = v1;
        }
    }
}

// ------------- Kernel 2: out = (Y + I-term) @ W^T + b ----------------------
// grid = N/16 = 384 blocks, 256 threads. Block handles 16 n-rows, all b, all o.
// Thread: fixed o = t&63; group g = t>>6 handles 32 (nn,b) pairs.
// W row cached in registers; Ysh reads are warp-broadcast; stores coalesced.
__global__ __launch_bounds__(256)
void out_kernel(const float* __restrict__ inputs,
                const float* __restrict__ W,
                const float* __restrict__ bias,
                float* __restrict__ out) {
    __shared__ float Ysh[3][16][128];   // 24 KB, identity pre-added

    const int n0 = blockIdx.x * 16;
    const int t  = threadIdx.x;
    const int o  = t & 63;
    const int g  = t >> 6;              // 0..3

    // fill Ysh: coalesced g_Y reads, identity folded in
    for (int idx = t; idx < 3 * 16 * 128; idx += 256) {
        const int kk = idx / (16 * 128);
        const int nn = (idx >> 7) & 15;
        const int c  = idx & 127;       // b*16 + d
        const int b  = c >> 4;
        const int d  = c & 15;
        const int n  = n0 + nn;
        Ysh[kk][nn][c] = g_Y[(size_t)kk * N_ * BD_ + (size_t)n * BD_ + c]
                       + inputs[((size_t)b * N_ + n) * D_ + d];
    }

    // cache W row + bias in registers
    float wreg[48];
    #pragma unroll
    for (int j = 0; j < 48; ++j) wreg[j] = W[o * 48 + j];
    const float bo = bias[o];

    __syncthreads();

    #pragma unroll 4
    for (int pp = 0; pp < 32; ++pp) {
        const int pair = g * 32 + pp;   // 0..127
        const int nn = pair >> 3;
        const int b  = pair & 7;
        const float* z = &Ysh[0][nn][b * 16];   // stride between k-planes: 16*128
        float acc = bo;
        #pragma unroll
        for (int j = 0; j < 48; ++j) {
            const int d  = j / 3;
            const int kk = j % 3;
            acc += z[kk * (16 * 128) + d] * wreg[j];
        }
        out[((size_t)b * N_ + n0 + nn) * O_ + o] = acc;
    }
}

// ------------- launch -------------------------------------------------------
extern "C" void kernel_launch(void* const* d_in, const int* in_sizes, int n_in,
                              void* d_out, int out_size) {
    const float* inputs = nullptr;
    const float* supports = nullptr;
    const float* W = nullptr;
    const float* bias = nullptr;
    for (int i = 0; i < n_in; ++i) {
        if      (in_sizes[i] == B_ * N_ * D_) inputs   = (const float*)d_in[i];
        else if (in_sizes[i] == K_ * N_ * N_) supports = (const float*)d_in[i];
        else if (in_sizes[i] == O_ * D_ * K_) W        = (const float*)d_in[i];
        else if (in_sizes[i] == O_)           bias     = (const float*)d_in[i];
    }
    float* out = (float*)d_out;

    cudaFuncSetAttribute(gemm_mma_kernel,
                         cudaFuncAttributeMaxDynamicSharedMemorySize, SMEM_BYTES);

    xsplit_kernel<<<(BD_ * N_ + 255) / 256, 256>>>(inputs);
    gemm_mma_kernel<<<dim3(N_ / 128, K_), 512, SMEM_BYTES>>>(supports);
    out_kernel<<<N_ / 16, 256>>>(inputs, W, bias, out);
}

// round 9
// speedup vs baseline: 4.3796x; 1.0104x over previous
#include <cuda_runtime.h>
#include <cuda_fp16.h>
#include <cstdint>

// Problem constants
#define B_  8
#define N_  6144
#define D_  16
#define K_  3
#define O_  64
#define BD_ 128             // B*D columns
#define TK2_ 128            // k-tile (two 64-wide subtiles)
#define NSTEP2_ (N_ / TK2_) // 48

// ------------- global scratch (no cudaMalloc allowed) ----------------------
__device__ __half g_Xf[(size_t)BD_ * N_];          // X^T fp16 [col j][k]
__device__ float  g_Y [(size_t)K_ * N_ * BD_];

// ------------- PTX helpers --------------------------------------------------
__device__ __forceinline__ unsigned smem_u32(const void* p) {
    return (unsigned)__cvta_generic_to_shared(p);
}
__device__ __forceinline__ void cp_async16(unsigned dst, const void* gsrc) {
    asm volatile("cp.async.cg.shared.global [%0], [%1], 16;\n" :: "r"(dst), "l"(gsrc));
}
__device__ __forceinline__ void cp_commit() {
    asm volatile("cp.async.commit_group;\n" ::: "memory");
}
template<int NW> __device__ __forceinline__ void cp_wait() {
    asm volatile("cp.async.wait_group %0;\n" :: "n"(NW) : "memory");
}
__device__ __forceinline__ void sts64(unsigned addr, unsigned long long v) {
    asm volatile("st.shared.b64 [%0], %1;" :: "r"(addr), "l"(v) : "memory");
}
__device__ __forceinline__ void ldsm_x4(unsigned& r0, unsigned& r1,
                                        unsigned& r2, unsigned& r3, unsigned addr) {
    asm volatile("ldmatrix.sync.aligned.m8n8.x4.shared.b16 {%0,%1,%2,%3}, [%4];"
                 : "=r"(r0), "=r"(r1), "=r"(r2), "=r"(r3) : "r"(addr));
}
// D(f32) += A(f16) * B(f16), m16n8k16, row.col
__device__ __forceinline__ void mma16816(float* d, const unsigned* a,
                                         const unsigned* b) {
    asm volatile(
        "mma.sync.aligned.m16n8k16.row.col.f32.f16.f16.f32 "
        "{%0,%1,%2,%3}, {%4,%5,%6,%7}, {%8,%9}, {%0,%1,%2,%3};"
        : "+f"(d[0]), "+f"(d[1]), "+f"(d[2]), "+f"(d[3])
        : "r"(a[0]), "r"(a[1]), "r"(a[2]), "r"(a[3]), "r"(b[0]), "r"(b[1]));
}

#define SMEM_SWIZZLE_128B(o) ((o) ^ (((o) >> 3) & 0x70))

// pack two floats -> fp16x2 (lo = x, hi = y)
__device__ __forceinline__ unsigned cvt_f16x2(float x, float y) {
    unsigned r;
    asm("cvt.rn.f16x2.f32 %0, %1, %2;" : "=r"(r) : "f"(y), "f"(x));
    return r;
}

// ------------- smem layout per block: 2 buf x (A:16KB + B:32KB) = 96KB ------
// A subtile h: 64x64 fp16 = 8KB. B subtile h: 128x64 fp16 = 16KB.
#define OFF_A(buf,h)  ((buf) * 49152 + (h) * 8192)
#define OFF_Bt(buf,h) ((buf) * 49152 + 16384 + (h) * 16384)
#define SMEM_BYTES 98304

// ------------- Kernel 0: X^T -> fp16 ----------------------------------------
__global__ void xsplit_kernel(const float* __restrict__ inputs) {
    int idx = blockIdx.x * blockDim.x + threadIdx.x;   // j*N_ + m
    if (idx >= BD_ * N_) return;
    int j = idx / N_;          // col = b*16 + d
    int m = idx % N_;
    int b = j >> 4, d = j & 15;
    float x = inputs[((size_t)b * N_ + m) * D_ + d];
    g_Xf[idx] = __float2half_rn(x);
}

// ------------- Kernel 1: fp16 GEMM via mma.sync, 2 CTAs/SM ------------------
// Block: C[64,128] tile of Y_k = sup_k @ X. grid = (96, 3) = 288 blocks.
// 256 threads / 8 warps in a 2x4 grid; warp tile 32x32 (2 m-tiles x 4 n-tiles).
__global__ __launch_bounds__(256, 2)
void gemm_mma_kernel(const float* __restrict__ supports) {
    extern __shared__ char smem_raw[];
    const unsigned sbase = smem_u32(smem_raw);

    const int t    = threadIdx.x;
    const int wid  = t >> 5;
    const int lane = t & 31;
    const int row0 = blockIdx.x * 64;

    const float* A = supports + (size_t)blockIdx.y * N_ * N_;
    float*       C = g_Y      + (size_t)blockIdx.y * N_ * BD_;

    const int wm0 = (wid >> 2) * 32;    // 0,32
    const int wn0 = (wid & 3) * 32;     // 0,32,64,96

    // loader mapping (A): 16 threads per row, float4 each
    const int a_sub = t >> 4;           // 0..15
    const int a_c4  = (t & 15) << 2;    // float col 0..60 within 64-k subtile

    // ldmatrix lane address components
    const int a_r  = lane & 15;
    const int a_k8 = (lane >> 4) << 3;
    const int b_n  = ((lane >> 4) << 3) + (lane & 7);
    const int b_k8 = ((lane >> 3) & 1) << 3;

    float acc[2][4][4];
    #pragma unroll
    for (int i = 0; i < 2; ++i)
        #pragma unroll
        for (int j = 0; j < 4; ++j)
            #pragma unroll
            for (int p = 0; p < 4; ++p) acc[i][j][p] = 0.f;

    float4 av[8];   // [h(2)][rowpass(4)]: rows (p&3)*16 + a_sub of subtile p>>2

    // ---- prologue: A(kt=0) LDG + B(kt=0) cp.async, convert+STS into buf0
    #pragma unroll
    for (int p = 0; p < 8; ++p) {
        const int h   = p >> 2;
        const int row = (p & 3) * 16 + a_sub;
        av[p] = __ldg(reinterpret_cast<const float4*>(
            &A[(size_t)(row0 + row) * N_ + h * 64 + a_c4]));
    }
    #pragma unroll
    for (int h = 0; h < 2; ++h)
        #pragma unroll
        for (int j = 0; j < 4; ++j) {
            const int c   = t + j * 256;       // 16B chunk (0..1023)
            const int r   = c >> 3;            // B row (n col) 0..127
            const int kin = (c & 7) << 3;
            const unsigned swz = SMEM_SWIZZLE_128B((unsigned)(c << 4));
            cp_async16(sbase + OFF_Bt(0, h) + swz,
                       &g_Xf[(size_t)r * N_ + h * 64 + kin]);
        }
    cp_commit();
    #pragma unroll
    for (int p = 0; p < 8; ++p) {
        const int h   = p >> 2;
        const int row = (p & 3) * 16 + a_sub;
        const unsigned boff = (unsigned)(row * 128 + (a_c4 << 1));
        const unsigned swz  = SMEM_SWIZZLE_128B(boff);
        unsigned h01 = cvt_f16x2(av[p].x, av[p].y);
        unsigned h23 = cvt_f16x2(av[p].z, av[p].w);
        sts64(sbase + OFF_A(0, h) + swz, ((unsigned long long)h23 << 32) | h01);
    }

    for (int kt = 0; kt < NSTEP2_; ++kt) {
        const int buf  = kt & 1;
        const int nbuf = buf ^ 1;

        cp_wait<0>();
        __syncthreads();   // buf tiles visible; prior compute done

        // issue loads for kt+1 into nbuf (overlap with compute below)
        if (kt + 1 < NSTEP2_) {
            const int kk2 = (kt + 1) * TK2_;
            #pragma unroll
            for (int p = 0; p < 8; ++p) {
                const int h   = p >> 2;
                const int row = (p & 3) * 16 + a_sub;
                av[p] = __ldg(reinterpret_cast<const float4*>(
                    &A[(size_t)(row0 + row) * N_ + kk2 + h * 64 + a_c4]));
            }
            #pragma unroll
            for (int h = 0; h < 2; ++h)
                #pragma unroll
                for (int j = 0; j < 4; ++j) {
                    const int c   = t + j * 256;
                    const int r   = c >> 3;
                    const int kin = (c & 7) << 3;
                    const unsigned swz = SMEM_SWIZZLE_128B((unsigned)(c << 4));
                    cp_async16(sbase + OFF_Bt(nbuf, h) + swz,
                               &g_Xf[(size_t)r * N_ + kk2 + h * 64 + kin]);
                }
            cp_commit();
        }

        // ---- compute on buf: 8 k16 steps (2 subtiles x 4), 8 MMAs each
        #pragma unroll
        for (int ks = 0; ks < 8; ++ks) {
            const int h    = ks >> 2;
            const int kk16 = (ks & 3) * 16;
            const unsigned a_base = sbase + OFF_A(buf, h);
            const unsigned b_base = sbase + OFF_Bt(buf, h);

            unsigned af[2][4];
            #pragma unroll
            for (int mt = 0; mt < 2; ++mt) {
                const unsigned off = SMEM_SWIZZLE_128B(
                    (unsigned)((wm0 + mt * 16 + a_r) * 128 + (kk16 + a_k8) * 2));
                ldsm_x4(af[mt][0], af[mt][1], af[mt][2], af[mt][3], a_base + off);
            }
            unsigned bf[4][2];
            #pragma unroll
            for (int np = 0; np < 2; ++np) {
                const unsigned off = SMEM_SWIZZLE_128B(
                    (unsigned)((wn0 + np * 16 + b_n) * 128 + (kk16 + b_k8) * 2));
                ldsm_x4(bf[np*2][0], bf[np*2][1], bf[np*2+1][0], bf[np*2+1][1],
                        b_base + off);
            }
            #pragma unroll
            for (int mt = 0; mt < 2; ++mt)
                #pragma unroll
                for (int nt = 0; nt < 4; ++nt)
                    mma16816(acc[mt][nt], af[mt], bf[nt]);
        }

        // convert prefetched A regs -> fp16 into nbuf
        if (kt + 1 < NSTEP2_) {
            #pragma unroll
            for (int p = 0; p < 8; ++p) {
                const int h   = p >> 2;
                const int row = (p & 3) * 16 + a_sub;
                const unsigned boff = (unsigned)(row * 128 + (a_c4 << 1));
                const unsigned swz  = SMEM_SWIZZLE_128B(boff);
                unsigned h01 = cvt_f16x2(av[p].x, av[p].y);
                unsigned h23 = cvt_f16x2(av[p].z, av[p].w);
                sts64(sbase + OFF_A(nbuf, h) + swz,
                      ((unsigned long long)h23 << 32) | h01);
            }
        }
    }

    // ---- epilogue: write accumulators to g_Y (fp32)
    const int lr = lane >> 2;
    const int lc = (lane & 3) << 1;
    #pragma unroll
    for (int mt = 0; mt < 2; ++mt) {
        #pragma unroll
        for (int nt = 0; nt < 4; ++nt) {
            const int m = row0 + wm0 + mt * 16 + lr;
            const int n = wn0 + nt * 8 + lc;
            float2 v0 = make_float2(acc[mt][nt][0], acc[mt][nt][1]);
            float2 v1 = make_float2(acc[mt][nt][2], acc[mt][nt][3]);
            *reinterpret_cast<float2*>(&C[(size_t)m * BD_ + n])       = v0;
            *reinterpret_cast<float2*>(&C[(size_t)(m + 8) * BD_ + n]) = v1;
        }
    }
}

// ------------- Kernel 2: out = (Y + I-term) @ W^T + b ----------------------
__global__ __launch_bounds__(256)
void out_kernel(const float* __restrict__ inputs,
                const float* __restrict__ W,
                const float* __restrict__ bias,
                float* __restrict__ out) {
    __shared__ float Ysh[3][16][128];   // 24 KB, identity pre-added

    const int n0 = blockIdx.x * 16;
    const int t  = threadIdx.x;
    const int o  = t & 63;
    const int g  = t >> 6;              // 0..3

    for (int idx = t; idx < 3 * 16 * 128; idx += 256) {
        const int kk = idx / (16 * 128);
        const int nn = (idx >> 7) & 15;
        const int c  = idx & 127;       // b*16 + d
        const int b  = c >> 4;
        const int d  = c & 15;
        const int n  = n0 + nn;
        Ysh[kk][nn][c] = g_Y[(size_t)kk * N_ * BD_ + (size_t)n * BD_ + c]
                       + inputs[((size_t)b * N_ + n) * D_ + d];
    }

    float wreg[48];
    #pragma unroll
    for (int j = 0; j < 48; ++j) wreg[j] = W[o * 48 + j];
    const float bo = bias[o];

    __syncthreads();

    #pragma unroll 4
    for (int pp = 0; pp < 32; ++pp) {
        const int pair = g * 32 + pp;   // 0..127
        const int nn = pair >> 3;
        const int b  = pair & 7;
        const float* z = &Ysh[0][nn][b * 16];
        float acc = bo;
        #pragma unroll
        for (int j = 0; j < 48; ++j) {
            const int d  = j / 3;
            const int kk = j % 3;
            acc += z[kk * (16 * 128) + d] * wreg[j];
        }
        out[((size_t)b * N_ + n0 + nn) * O_ + o] = acc;
    }
}

// ------------- launch -------------------------------------------------------
extern "C" void kernel_launch(void* const* d_in, const int* in_sizes, int n_in,
                              void* d_out, int out_size) {
    const float* inputs = nullptr;
    const float* supports = nullptr;
    const float* W = nullptr;
    const float* bias = nullptr;
    for (int i = 0; i < n_in; ++i) {
        if      (in_sizes[i] == B_ * N_ * D_) inputs   = (const float*)d_in[i];
        else if (in_sizes[i] == K_ * N_ * N_) supports = (const float*)d_in[i];
        else if (in_sizes[i] == O_ * D_ * K_) W        = (const float*)d_in[i];
        else if (in_sizes[i] == O_)           bias     = (const float*)d_in[i];
    }
    float* out = (float*)d_out;

    cudaFuncSetAttribute(gemm_mma_kernel,
                         cudaFuncAttributeMaxDynamicSharedMemorySize, SMEM_BYTES);

    xsplit_kernel<<<(BD_ * N_ + 255) / 256, 256>>>(inputs);
    gemm_mma_kernel<<<dim3(N_ / 64, K_), 256, SMEM_BYTES>>>(supports);
    out_kernel<<<N_ / 16, 256>>>(inputs, W, bias, out);
}

// round 10
// speedup vs baseline: 4.5212x; 1.0323x over previous
#include <cuda_runtime.h>
#include <cuda_fp16.h>
#include <cstdint>

// Problem constants
#define B_  8
#define N_  6144
#define D_  16
#define K_  3
#define O_  64
#define BD_ 128             // B*D columns
#define TK2_ 128            // k-tile (two 64-wide subtiles)
#define NSTEP2_ (N_ / TK2_) // 48

// ------------- global scratch (no cudaMalloc allowed) ----------------------
__device__ __half g_Xf[(size_t)BD_ * N_];          // X^T fp16 [col j][k]
__device__ float  g_Y [(size_t)K_ * N_ * BD_];

// ------------- PTX helpers --------------------------------------------------
__device__ __forceinline__ unsigned smem_u32(const void* p) {
    return (unsigned)__cvta_generic_to_shared(p);
}
__device__ __forceinline__ void cp_async16(unsigned dst, const void* gsrc) {
    asm volatile("cp.async.cg.shared.global [%0], [%1], 16;\n" :: "r"(dst), "l"(gsrc));
}
__device__ __forceinline__ void cp_commit() {
    asm volatile("cp.async.commit_group;\n" ::: "memory");
}
template<int NW> __device__ __forceinline__ void cp_wait() {
    asm volatile("cp.async.wait_group %0;\n" :: "n"(NW) : "memory");
}
__device__ __forceinline__ void sts64(unsigned addr, unsigned long long v) {
    asm volatile("st.shared.b64 [%0], %1;" :: "r"(addr), "l"(v) : "memory");
}
__device__ __forceinline__ void ldsm_x4(unsigned& r0, unsigned& r1,
                                        unsigned& r2, unsigned& r3, unsigned addr) {
    asm volatile("ldmatrix.sync.aligned.m8n8.x4.shared.b16 {%0,%1,%2,%3}, [%4];"
                 : "=r"(r0), "=r"(r1), "=r"(r2), "=r"(r3) : "r"(addr));
}
// D(f32) += A(f16) * B(f16), m16n8k16, row.col
__device__ __forceinline__ void mma16816(float* d, const unsigned* a,
                                         const unsigned* b) {
    asm volatile(
        "mma.sync.aligned.m16n8k16.row.col.f32.f16.f16.f32 "
        "{%0,%1,%2,%3}, {%4,%5,%6,%7}, {%8,%9}, {%0,%1,%2,%3};"
        : "+f"(d[0]), "+f"(d[1]), "+f"(d[2]), "+f"(d[3])
        : "r"(a[0]), "r"(a[1]), "r"(a[2]), "r"(a[3]), "r"(b[0]), "r"(b[1]));
}

#define SMEM_SWIZZLE_128B(o) ((o) ^ (((o) >> 3) & 0x70))

// pack two floats -> fp16x2 (lo = x, hi = y)
__device__ __forceinline__ unsigned cvt_f16x2(float x, float y) {
    unsigned r;
    asm("cvt.rn.f16x2.f32 %0, %1, %2;" : "=r"(r) : "f"(y), "f"(x));
    return r;
}

// ------------- smem layout per block: 2 buf x (A:16KB + B:32KB) = 96KB ------
#define OFF_A(buf,h)  ((buf) * 49152 + (h) * 8192)
#define OFF_Bt(buf,h) ((buf) * 49152 + 16384 + (h) * 16384)
#define SMEM_BYTES 98304

// ------------- Kernel 0: X^T -> fp16 (smem transpose, coalesced) ------------
// Block: 64 m-rows x 128 (b*16+d) cols. grid = N/64 = 96. 256 threads.
__global__ __launch_bounds__(256)
void xsplit_kernel(const float* __restrict__ inputs) {
    __shared__ float S[64][129];    // +1 pad: conflict-free column reads

    const int t  = threadIdx.x;
    const int m0 = blockIdx.x * 64;

    // coalesced load: consecutive t -> consecutive (b,d) within a row
    #pragma unroll
    for (int r = 0; r < 32; ++r) {
        const int idx = t + r * 256;       // 0..8191
        const int ml  = idx >> 7;          // m_local 0..63
        const int c   = idx & 127;         // b*16+d
        const int b   = c >> 4, d = c & 15;
        S[ml][c] = inputs[((size_t)b * N_ + m0 + ml) * D_ + d];
    }
    __syncthreads();

    // each thread: fixed c, 32 m's (4 groups of 8), 16B vector stores
    const int c    = t & 127;
    const int half = t >> 7;               // 0..1
    #pragma unroll
    for (int s = 0; s < 4; ++s) {
        const int ms = half * 32 + s * 8;  // m_local start
        uint4 v;
        v.x = cvt_f16x2(S[ms + 0][c], S[ms + 1][c]);
        v.y = cvt_f16x2(S[ms + 2][c], S[ms + 3][c]);
        v.z = cvt_f16x2(S[ms + 4][c], S[ms + 5][c]);
        v.w = cvt_f16x2(S[ms + 6][c], S[ms + 7][c]);
        *reinterpret_cast<uint4*>(&g_Xf[(size_t)c * N_ + m0 + ms]) = v;
    }
}

// ------------- Kernel 1: fp16 GEMM via mma.sync, 2 CTAs/SM ------------------
// Block: C[64,128] tile of Y_k = sup_k @ X. grid = (96, 3) = 288 blocks.
// 256 threads / 8 warps in a 2x4 grid; warp tile 32x32 (2 m-tiles x 4 n-tiles).
__global__ __launch_bounds__(256, 2)
void gemm_mma_kernel(const float* __restrict__ supports) {
    extern __shared__ char smem_raw[];
    const unsigned sbase = smem_u32(smem_raw);

    const int t    = threadIdx.x;
    const int wid  = t >> 5;
    const int lane = t & 31;
    const int row0 = blockIdx.x * 64;

    const float* A = supports + (size_t)blockIdx.y * N_ * N_;
    float*       C = g_Y      + (size_t)blockIdx.y * N_ * BD_;

    const int wm0 = (wid >> 2) * 32;    // 0,32
    const int wn0 = (wid & 3) * 32;     // 0,32,64,96

    // loader mapping (A): 16 threads per row, float4 each
    const int a_sub = t >> 4;           // 0..15
    const int a_c4  = (t & 15) << 2;    // float col 0..60 within 64-k subtile

    // ldmatrix lane address components
    const int a_r  = lane & 15;
    const int a_k8 = (lane >> 4) << 3;
    const int b_n  = ((lane >> 4) << 3) + (lane & 7);
    const int b_k8 = ((lane >> 3) & 1) << 3;

    float acc[2][4][4];
    #pragma unroll
    for (int i = 0; i < 2; ++i)
        #pragma unroll
        for (int j = 0; j < 4; ++j)
            #pragma unroll
            for (int p = 0; p < 4; ++p) acc[i][j][p] = 0.f;

    float4 av[8];   // [h(2)][rowpass(4)]: rows (p&3)*16 + a_sub of subtile p>>2

    // ---- prologue: A(kt=0) LDG + B(kt=0) cp.async, convert+STS into buf0
    #pragma unroll
    for (int p = 0; p < 8; ++p) {
        const int h   = p >> 2;
        const int row = (p & 3) * 16 + a_sub;
        av[p] = __ldg(reinterpret_cast<const float4*>(
            &A[(size_t)(row0 + row) * N_ + h * 64 + a_c4]));
    }
    #pragma unroll
    for (int h = 0; h < 2; ++h)
        #pragma unroll
        for (int j = 0; j < 4; ++j) {
            const int c   = t + j * 256;       // 16B chunk (0..1023)
            const int r   = c >> 3;            // B row (n col) 0..127
            const int kin = (c & 7) << 3;
            const unsigned swz = SMEM_SWIZZLE_128B((unsigned)(c << 4));
            cp_async16(sbase + OFF_Bt(0, h) + swz,
                       &g_Xf[(size_t)r * N_ + h * 64 + kin]);
        }
    cp_commit();
    #pragma unroll
    for (int p = 0; p < 8; ++p) {
        const int h   = p >> 2;
        const int row = (p & 3) * 16 + a_sub;
        const unsigned boff = (unsigned)(row * 128 + (a_c4 << 1));
        const unsigned swz  = SMEM_SWIZZLE_128B(boff);
        unsigned h01 = cvt_f16x2(av[p].x, av[p].y);
        unsigned h23 = cvt_f16x2(av[p].z, av[p].w);
        sts64(sbase + OFF_A(0, h) + swz, ((unsigned long long)h23 << 32) | h01);
    }

    for (int kt = 0; kt < NSTEP2_; ++kt) {
        const int buf  = kt & 1;
        const int nbuf = buf ^ 1;

        // A LDGs for kt+1 issued BEFORE the wait/barrier: register-only,
        // prior iteration's STS already consumed av (program order), so this
        // only lengthens their DRAM lead time.
        if (kt + 1 < NSTEP2_) {
            const int kk2 = (kt + 1) * TK2_;
            #pragma unroll
            for (int p = 0; p < 8; ++p) {
                const int h   = p >> 2;
                const int row = (p & 3) * 16 + a_sub;
                av[p] = __ldg(reinterpret_cast<const float4*>(
                    &A[(size_t)(row0 + row) * N_ + kk2 + h * 64 + a_c4]));
            }
        }

        cp_wait<0>();
        __syncthreads();   // buf tiles visible; prior compute done

        // B cp.async for kt+1 into nbuf (must be after the barrier)
        if (kt + 1 < NSTEP2_) {
            const int kk2 = (kt + 1) * TK2_;
            #pragma unroll
            for (int h = 0; h < 2; ++h)
                #pragma unroll
                for (int j = 0; j < 4; ++j) {
                    const int c   = t + j * 256;
                    const int r   = c >> 3;
                    const int kin = (c & 7) << 3;
                    const unsigned swz = SMEM_SWIZZLE_128B((unsigned)(c << 4));
                    cp_async16(sbase + OFF_Bt(nbuf, h) + swz,
                               &g_Xf[(size_t)r * N_ + kk2 + h * 64 + kin]);
                }
            cp_commit();
        }

        // ---- compute on buf: 8 k16 steps (2 subtiles x 4), 8 MMAs each
        #pragma unroll
        for (int ks = 0; ks < 8; ++ks) {
            const int h    = ks >> 2;
            const int kk16 = (ks & 3) * 16;
            const unsigned a_base = sbase + OFF_A(buf, h);
            const unsigned b_base = sbase + OFF_Bt(buf, h);

            unsigned af[2][4];
            #pragma unroll
            for (int mt = 0; mt < 2; ++mt) {
                const unsigned off = SMEM_SWIZZLE_128B(
                    (unsigned)((wm0 + mt * 16 + a_r) * 128 + (kk16 + a_k8) * 2));
                ldsm_x4(af[mt][0], af[mt][1], af[mt][2], af[mt][3], a_base + off);
            }
            unsigned bf[4][2];
            #pragma unroll
            for (int np = 0; np < 2; ++np) {
                const unsigned off = SMEM_SWIZZLE_128B(
                    (unsigned)((wn0 + np * 16 + b_n) * 128 + (kk16 + b_k8) * 2));
                ldsm_x4(bf[np*2][0], bf[np*2][1], bf[np*2+1][0], bf[np*2+1][1],
                        b_base + off);
            }
            #pragma unroll
            for (int mt = 0; mt < 2; ++mt)
                #pragma unroll
                for (int nt = 0; nt < 4; ++nt)
                    mma16816(acc[mt][nt], af[mt], bf[nt]);
        }

        // convert prefetched A regs -> fp16 into nbuf
        if (kt + 1 < NSTEP2_) {
            #pragma unroll
            for (int p = 0; p < 8; ++p) {
                const int h   = p >> 2;
                const int row = (p & 3) * 16 + a_sub;
                const unsigned boff = (unsigned)(row * 128 + (a_c4 << 1));
                const unsigned swz  = SMEM_SWIZZLE_128B(boff);
                unsigned h01 = cvt_f16x2(av[p].x, av[p].y);
                unsigned h23 = cvt_f16x2(av[p].z, av[p].w);
                sts64(sbase + OFF_A(nbuf, h) + swz,
                      ((unsigned long long)h23 << 32) | h01);
            }
        }
    }

    // ---- epilogue: write accumulators to g_Y (fp32)
    const int lr = lane >> 2;
    const int lc = (lane & 3) << 1;
    #pragma unroll
    for (int mt = 0; mt < 2; ++mt) {
        #pragma unroll
        for (int nt = 0; nt < 4; ++nt) {
            const int m = row0 + wm0 + mt * 16 + lr;
            const int n = wn0 + nt * 8 + lc;
            float2 v0 = make_float2(acc[mt][nt][0], acc[mt][nt][1]);
            float2 v1 = make_float2(acc[mt][nt][2], acc[mt][nt][3]);
            *reinterpret_cast<float2*>(&C[(size_t)m * BD_ + n])       = v0;
            *reinterpret_cast<float2*>(&C[(size_t)(m + 8) * BD_ + n]) = v1;
        }
    }
}

// ------------- Kernel 2: out = (Y + I-term) @ W^T + b ----------------------
__global__ __launch_bounds__(256)
void out_kernel(const float* __restrict__ inputs,
                const float* __restrict__ W,
                const float* __restrict__ bias,
                float* __restrict__ out) {
    __shared__ float Ysh[3][16][128];   // 24 KB, identity pre-added

    const int n0 = blockIdx.x * 16;
    const int t  = threadIdx.x;
    const int o  = t & 63;
    const int g  = t >> 6;              // 0..3

    for (int idx = t; idx < 3 * 16 * 128; idx += 256) {
        const int kk = idx / (16 * 128);
        const int nn = (idx >> 7) & 15;
        const int c  = idx & 127;       // b*16 + d
        const int b  = c >> 4;
        const int d  = c & 15;
        const int n  = n0 + nn;
        Ysh[kk][nn][c] = g_Y[(size_t)kk * N_ * BD_ + (size_t)n * BD_ + c]
                       + inputs[((size_t)b * N_ + n) * D_ + d];
    }

    float wreg[48];
    #pragma unroll
    for (int j = 0; j < 48; ++j) wreg[j] = W[o * 48 + j];
    const float bo = bias[o];

    __syncthreads();

    #pragma unroll 4
    for (int pp = 0; pp < 32; ++pp) {
        const int pair = g * 32 + pp;   // 0..127
        const int nn = pair >> 3;
        const int b  = pair & 7;
        const float* z = &Ysh[0][nn][b * 16];
        float acc = bo;
        #pragma unroll
        for (int j = 0; j < 48; ++j) {
            const int d  = j / 3;
            const int kk = j % 3;
            acc += z[kk * (16 * 128) + d] * wreg[j];
        }
        out[((size_t)b * N_ + n0 + nn) * O_ + o] = acc;
    }
}

// ------------- launch -------------------------------------------------------
extern "C" void kernel_launch(void* const* d_in, const int* in_sizes, int n_in,
                              void* d_out, int out_size) {
    const float* inputs = nullptr;
    const float* supports = nullptr;
    const float* W = nullptr;
    const float* bias = nullptr;
    for (int i = 0; i < n_in; ++i) {
        if      (in_sizes[i] == B_ * N_ * D_) inputs   = (const float*)d_in[i];
        else if (in_sizes[i] == K_ * N_ * N_) supports = (const float*)d_in[i];
        else if (in_sizes[i] == O_ * D_ * K_) W        = (const float*)d_in[i];
        else if (in_sizes[i] == O_)           bias     = (const float*)d_in[i];
    }
    float* out = (float*)d_out;

    cudaFuncSetAttribute(gemm_mma_kernel,
                         cudaFuncAttributeMaxDynamicSharedMemorySize, SMEM_BYTES);

    xsplit_kernel<<<N_ / 64, 256>>>(inputs);
    gemm_mma_kernel<<<dim3(N_ / 64, K_), 256, SMEM_BYTES>>>(supports);
    out_kernel<<<N_ / 16, 256>>>(inputs, W, bias, out);
}